// round 3
// baseline (speedup 1.0000x reference)
#include <cuda_runtime.h>
#include <math.h>
#include <stdint.h>

#define G    8
#define NBG  1024
#define APB  4
#define HID  512
#define ES   64
#define KNN  9
#define LAY  3
#define NB   (G*NBG)        // 8192
#define NU   (NB*APB)       // 32768
#define NE   (2*KNN)        // 18 edges per dst block

// output layout (float32, concatenated reference outputs)
#define OFF_E    0
#define OFF_PN   8
#define OFF_UR   98312            // 8 + 32768*3
#define OFF_BR   16875528         // + 32768*512
#define OFF_GR   21069832         // + 8192*512
#define OFF_LOSS 21073928         // + 8*512

// ---------------- scratch (static device globals; no allocations) ----------
__device__ float4 g_ZpS[NU];          // x,y,z,sq
__device__ float  g_H0[NU*HID];       // 64 MB
__device__ float  g_h[NB*HID];
__device__ float  g_hW[NB*HID];
__device__ float  g_agg[NB*HID];
__device__ float  g_t[NB*HID];
__device__ float  g_Zb0[NB*3];
__device__ float  g_ZbA[NB*3];
__device__ float  g_ZbB[NB*3];
__device__ int    g_nbr[NB*NE];
__device__ float  g_eW[LAY*2*HID];
__device__ float  g_eblk[NB];

__device__ __forceinline__ float silu_f(float x){ return x / (1.0f + expf(-x)); }

// ---------------- 1. perturb + sq ----------------
__global__ void k_perturb(const float* __restrict__ Z, const float* __restrict__ noise,
                          const int* __restrict__ nl, const float* __restrict__ sigmas)
{
    int u = blockIdx.x*blockDim.x + threadIdx.x;
    if (u >= NU) return;
    int g = u >> 12;                       // u / (NBG*APB)
    float s = sigmas[nl[g]];
    float x = Z[u*3+0] + noise[u*3+0]*s;
    float y = Z[u*3+1] + noise[u*3+1]*s;
    float z = Z[u*3+2] + noise[u*3+2]*s;
    float4 v; v.x=x; v.y=y; v.z=z; v.w = x*x + y*y + z*z;
    g_ZpS[u] = v;
}

// ---------------- 2. block coordinate means ----------------
__global__ void k_zb0()
{
    int b = blockIdx.x*blockDim.x + threadIdx.x;
    if (b >= NB) return;
    float4 a0 = g_ZpS[b*4+0], a1 = g_ZpS[b*4+1], a2 = g_ZpS[b*4+2], a3 = g_ZpS[b*4+3];
    float x = (((a0.x+a1.x)+a2.x)+a3.x)*0.25f;
    float y = (((a0.y+a1.y)+a2.y)+a3.y)*0.25f;
    float z = (((a0.z+a1.z)+a2.z)+a3.z)*0.25f;
    g_Zb0[b*3+0]=x; g_Zb0[b*3+1]=y; g_Zb0[b*3+2]=z;
    g_ZbA[b*3+0]=x; g_ZbA[b*3+1]=y; g_ZbA[b*3+2]=z;
}

// ---------------- 3. H0 = atom_emb[A] + pos_emb[P] + block_emb[B[blk]] -----
__global__ void k_H0(const int* __restrict__ A, const int* __restrict__ P,
                     const int* __restrict__ B,
                     const float* __restrict__ ae, const float* __restrict__ pe,
                     const float* __restrict__ be)
{
    int idx = blockIdx.x*blockDim.x + threadIdx.x;    // over NU*128 float4
    if (idx >= NU*(HID/4)) return;
    int u = idx >> 7;
    int c = idx & 127;
    const float4* ae4 = (const float4*)ae;
    const float4* pe4 = (const float4*)pe;
    const float4* be4 = (const float4*)be;
    float4 a = ae4[A[u]*(HID/4)+c];
    float4 p = pe4[P[u]*(HID/4)+c];
    float4 b = be4[B[u>>2]*(HID/4)+c];
    float4 r; r.x=a.x+p.x+b.x; r.y=a.y+p.y+b.y; r.z=a.z+p.z+b.z; r.w=a.w+p.w+b.w;
    ((float4*)g_H0)[idx] = r;
}

// ---------------- 4. h = block mean of H0 ----------------
__global__ void k_hinit()
{
    int idx = blockIdx.x*blockDim.x + threadIdx.x;    // over NB*128 float4
    if (idx >= NB*(HID/4)) return;
    int b = idx >> 7;
    int c = idx & 127;
    const float4* H = (const float4*)g_H0;
    float4 s0 = H[(b*4+0)*(HID/4)+c];
    float4 s1 = H[(b*4+1)*(HID/4)+c];
    float4 s2 = H[(b*4+2)*(HID/4)+c];
    float4 s3 = H[(b*4+3)*(HID/4)+c];
    float4 r;
    r.x = (((s0.x+s1.x)+s2.x)+s3.x)*0.25f;
    r.y = (((s0.y+s1.y)+s2.y)+s3.y)*0.25f;
    r.z = (((s0.z+s1.z)+s2.z)+s3.z)*0.25f;
    r.w = (((s0.w+s1.w)+s2.w)+s3.w)*0.25f;
    ((float4*)g_h)[idx] = r;
}

// ---------------- 5. eW[l][type][c] = edge_emb[type] @ We[l] ----------------
__global__ void k_ew(const float* __restrict__ ee, const float* __restrict__ We)
{
    int idx = blockIdx.x*blockDim.x + threadIdx.x;
    if (idx >= LAY*2*HID) return;
    int l = idx / (2*HID);
    int r = idx % (2*HID);
    int t = r / HID;
    int c = r % HID;
    float acc = 0.f;
    #pragma unroll 8
    for (int k = 0; k < ES; k++)
        acc += ee[t*ES+k] * We[(l*ES+k)*HID + c];
    g_eW[idx] = acc;
}

// ---------------- 6. KNN ----------------
__device__ __forceinline__ void ins9(float D, int j, float* bd, int* bi)
{
    if (D >= bd[8]) return;
    int p = 8;
    while (p > 0 && bd[p-1] > D) { bd[p]=bd[p-1]; bi[p]=bi[p-1]; --p; }
    bd[p]=D; bi[p]=j;
}

#define KNN_SMEM (NBG*APB*16 + NBG*4)

__global__ void k_knn(const int* __restrict__ seg)
{
    extern __shared__ float4 sm[];                 // 4096 atoms (x,y,z,sq)
    int* sseg = (int*)&sm[NBG*APB];
    int g = blockIdx.y;
    int chunk = blockIdx.x;
    int base_atom = g*NBG*APB;
    for (int i = threadIdx.x; i < NBG*APB; i += blockDim.x) sm[i] = g_ZpS[base_atom + i];
    for (int i = threadIdx.x; i < NBG; i += blockDim.x) sseg[i] = seg[g*NBG + i];
    __syncthreads();

    int ib = chunk*256 + threadIdx.x;              // local dst block
    float4 o0 = sm[ib*4+0], o1 = sm[ib*4+1], o2 = sm[ib*4+2], o3 = sm[ib*4+3];
    int myseg = sseg[ib];

    float bd0[KNN], bd1[KNN]; int bi0[KNN], bi1[KNN];
    #pragma unroll
    for (int k = 0; k < KNN; k++) { bd0[k]=3.0e38f; bd1[k]=3.0e38f; bi0[k]=0; bi1[k]=0; }

    for (int j = 0; j < NBG; j++) {
        float4 c0 = sm[j*4+0], c1 = sm[j*4+1], c2 = sm[j*4+2], c3 = sm[j*4+3];
        #define DD(o,c) ((o).w + (c).w - 2.0f*((o).x*(c).x + (o).y*(c).y + (o).z*(c).z))
        float d = DD(o0,c0);
        d = fminf(d, DD(o0,c1)); d = fminf(d, DD(o0,c2)); d = fminf(d, DD(o0,c3));
        d = fminf(d, DD(o1,c0)); d = fminf(d, DD(o1,c1)); d = fminf(d, DD(o1,c2)); d = fminf(d, DD(o1,c3));
        d = fminf(d, DD(o2,c0)); d = fminf(d, DD(o2,c1)); d = fminf(d, DD(o2,c2)); d = fminf(d, DD(o2,c3));
        d = fminf(d, DD(o3,c0)); d = fminf(d, DD(o3,c1)); d = fminf(d, DD(o3,c2)); d = fminf(d, DD(o3,c3));
        #undef DD
        if (sseg[j] == myseg) {
            if (j != ib) ins9(d, j, bd0, bi0);
        } else {
            ins9(d, j, bd1, bi1);
        }
    }
    int dblk = g*NBG + ib;
    #pragma unroll
    for (int k = 0; k < KNN; k++) {
        g_nbr[dblk*NE + k]       = g*NBG + bi0[k];
        g_nbr[dblk*NE + KNN + k] = g*NBG + bi1[k];
    }
}

// ---------------- 7. SGEMM: C[8192,512] = op(A)[8192,512] @ B[512,512] ------
// EPI 0: C = acc;  EPI 1: C = addC + silu(acc);  EPI 2: C = acc + bias[col]
template<int SILU_A, int EPI>
__global__ __launch_bounds__(256) void sgemm_k(
    const float* __restrict__ A, const float* __restrict__ Bm,
    float* __restrict__ C, const float* __restrict__ addC,
    const float* __restrict__ bias)
{
    const int N = HID, Kd = HID;
    __shared__ float As[8][128];
    __shared__ float Bs[8][128];
    int tid = threadIdx.x;
    int brow = blockIdx.y * 128;
    int bcol = blockIdx.x * 128;
    int a_r = tid >> 1, a_c = (tid & 1) * 4;
    int b_r = tid >> 5, b_c = (tid & 31) * 4;
    int ty = tid >> 4, tx = tid & 15;
    float acc[8][8];
    #pragma unroll
    for (int i=0;i<8;i++){
        #pragma unroll
        for (int j=0;j<8;j++) acc[i][j]=0.f;
    }

    for (int k0 = 0; k0 < Kd; k0 += 8) {
        float4 av = *(const float4*)(A + (size_t)(brow+a_r)*Kd + k0 + a_c);
        if (SILU_A){ av.x=silu_f(av.x); av.y=silu_f(av.y); av.z=silu_f(av.z); av.w=silu_f(av.w); }
        As[a_c+0][a_r]=av.x; As[a_c+1][a_r]=av.y; As[a_c+2][a_r]=av.z; As[a_c+3][a_r]=av.w;
        *(float4*)&Bs[b_r][b_c] = *(const float4*)(Bm + (size_t)(k0+b_r)*N + bcol + b_c);
        __syncthreads();
        #pragma unroll
        for (int k=0;k<8;k++){
            float4 a0 = *(const float4*)&As[k][ty*8];
            float4 a1 = *(const float4*)&As[k][ty*8+4];
            float4 b0 = *(const float4*)&Bs[k][tx*8];
            float4 b1 = *(const float4*)&Bs[k][tx*8+4];
            float ar[8] = {a0.x,a0.y,a0.z,a0.w,a1.x,a1.y,a1.z,a1.w};
            float br[8] = {b0.x,b0.y,b0.z,b0.w,b1.x,b1.y,b1.z,b1.w};
            #pragma unroll
            for (int i=0;i<8;i++){
                #pragma unroll
                for (int j=0;j<8;j++) acc[i][j] += ar[i]*br[j];
            }
        }
        __syncthreads();
    }
    #pragma unroll
    for (int i=0;i<8;i++){
        int row = brow + ty*8 + i;
        #pragma unroll
        for (int j=0;j<8;j++){
            int col = bcol + tx*8 + j;
            float v = acc[i][j];
            if (EPI == 1) v = addC[(size_t)row*N+col] + silu_f(v);
            if (EPI == 2) v = v + bias[col];
            C[(size_t)row*N+col] = v;
        }
    }
}

// ---------------- 8. fused edge/message kernel ----------------
__global__ __launch_bounds__(128) void k_edge(
    const float* __restrict__ wz_l, const float* __restrict__ eWl,
    const float* __restrict__ Zb_old, float* __restrict__ Zb_new)
{
    int d = blockIdx.x;
    int tid = threadIdx.x;                      // 128 threads, 4 channels each
    const float4* hW4 = (const float4*)g_hW;
    float4 hd  = hW4[(size_t)d*128 + tid];
    float4 wzv = ((const float4*)wz_l)[tid];
    float4 ew0 = ((const float4*)eWl)[tid];
    float4 ew1 = ((const float4*)(eWl + HID))[tid];
    float4 ag = make_float4(0.f,0.f,0.f,0.f);

    __shared__ float sred[4];
    __shared__ int snbr[NE];
    if (tid < NE) snbr[tid] = g_nbr[d*NE + tid];
    float Zdx=0.f, Zdy=0.f, Zdz=0.f, zx=0.f, zy=0.f, zz=0.f;
    if (tid == 0){ Zdx = Zb_old[d*3+0]; Zdy = Zb_old[d*3+1]; Zdz = Zb_old[d*3+2]; }
    __syncthreads();

    for (int e = 0; e < NE; e++) {
        int s = snbr[e];
        float4 ew = (e < KNN) ? ew0 : ew1;
        float4 hs = hW4[(size_t)s*128 + tid];
        float m0 = silu_f(hs.x + hd.x + ew.x);
        float m1 = silu_f(hs.y + hd.y + ew.y);
        float m2 = silu_f(hs.z + hd.z + ew.z);
        float m3 = silu_f(hs.w + hd.w + ew.w);
        ag.x += m0; ag.y += m1; ag.z += m2; ag.w += m3;
        float p = m0*wzv.x + m1*wzv.y + m2*wzv.z + m3*wzv.w;
        #pragma unroll
        for (int off = 16; off; off >>= 1) p += __shfl_down_sync(0xffffffffu, p, off);
        if ((tid & 31) == 0) sred[tid >> 5] = p;
        __syncthreads();
        if (tid == 0) {
            float coef = tanhf(sred[0]+sred[1]+sred[2]+sred[3]);
            zx += (Zb_old[s*3+0] - Zdx)*coef;
            zy += (Zb_old[s*3+1] - Zdy)*coef;
            zz += (Zb_old[s*3+2] - Zdz)*coef;
        }
        __syncthreads();
    }
    ((float4*)g_agg)[(size_t)d*128 + tid] = ag;
    if (tid == 0) {
        const float inv = 1.0f / (2*KNN);
        Zb_new[d*3+0] = Zdx + zx*inv;
        Zb_new[d*3+1] = Zdy + zy*inv;
        Zb_new[d*3+2] = Zdz + zz*inv;
    }
}

// ---------------- 9. energy head ----------------
__global__ __launch_bounds__(128) void k_eblk(const float* __restrict__ W2)
{
    int b = blockIdx.x;
    int tid = threadIdx.x;
    float4 tv = ((const float4*)g_t)[(size_t)b*128 + tid];
    float4 w  = ((const float4*)W2)[tid];
    float p = silu_f(tv.x)*w.x + silu_f(tv.y)*w.y + silu_f(tv.z)*w.z + silu_f(tv.w)*w.w;
    __shared__ float sred[4];
    #pragma unroll
    for (int off = 16; off; off >>= 1) p += __shfl_down_sync(0xffffffffu, p, off);
    if ((tid & 31) == 0) sred[tid >> 5] = p;
    __syncthreads();
    if (tid == 0) g_eblk[b] = sred[0]+sred[1]+sred[2]+sred[3];
}

__global__ __launch_bounds__(256) void k_energy(float* __restrict__ out)
{
    int g = blockIdx.x;
    int tid = threadIdx.x;
    float p = 0.f;
    #pragma unroll
    for (int k = 0; k < 4; k++) p += g_eblk[g*NBG + k*256 + tid];
    __shared__ float sred[8];
    #pragma unroll
    for (int off = 16; off; off >>= 1) p += __shfl_down_sync(0xffffffffu, p, off);
    if ((tid & 31) == 0) sred[tid >> 5] = p;
    __syncthreads();
    if (tid == 0) {
        float s = 0.f;
        #pragma unroll
        for (int w = 0; w < 8; w++) s += sred[w];
        out[OFF_E + g] = s;
        if (g == 0) out[OFF_LOSS] = 0.f;     // zero loss accumulator (runs before k_noise_loss)
    }
}

// ---------------- 10. graph_repr ----------------
__global__ __launch_bounds__(512) void k_graph(float* __restrict__ out)
{
    int g = blockIdx.x;
    int tid = threadIdx.x;       // channel
    float acc = 0.f;
    const float* hp = g_h + (size_t)g*NBG*HID + tid;
    for (int b = 0; b < NBG; b++) acc += hp[(size_t)b*HID];
    out[OFF_GR + g*HID + tid] = acc;
}

// ---------------- 11. pred_noise + loss ----------------
__global__ __launch_bounds__(256) void k_noise_loss(const float* __restrict__ noise,
                                                    float* __restrict__ out)
{
    int u = blockIdx.x*blockDim.x + threadIdx.x;
    float local = 0.f;
    if (u < NU) {
        int b = u >> 2;
        float dx = g_ZbB[b*3+0] - g_Zb0[b*3+0];
        float dy = g_ZbB[b*3+1] - g_Zb0[b*3+1];
        float dz = g_ZbB[b*3+2] - g_Zb0[b*3+2];
        out[OFF_PN + u*3+0] = dx;
        out[OFF_PN + u*3+1] = dy;
        out[OFF_PN + u*3+2] = dz;
        float ex = dx - noise[u*3+0];
        float ey = dy - noise[u*3+1];
        float ez = dz - noise[u*3+2];
        local = ex*ex + ey*ey + ez*ez;
    }
    __shared__ float sred[8];
    float p = local;
    #pragma unroll
    for (int off = 16; off; off >>= 1) p += __shfl_down_sync(0xffffffffu, p, off);
    if ((threadIdx.x & 31) == 0) sred[threadIdx.x >> 5] = p;
    __syncthreads();
    if (threadIdx.x == 0) {
        float s = 0.f;
        #pragma unroll
        for (int w = 0; w < 8; w++) s += sred[w];
        atomicAdd(out + OFF_LOSS, s * 0.0625f);   // 0.5/G
    }
}

// ---------------- 12. unit_repr & block_repr ----------------
__global__ void k_unit(float* __restrict__ out)
{
    int idx = blockIdx.x*blockDim.x + threadIdx.x;    // NU*128 float4
    if (idx >= NU*(HID/4)) return;
    int u = idx >> 7;
    int c = idx & 127;
    float4 h0 = ((const float4*)g_H0)[idx];
    float4 hb = ((const float4*)g_h)[(size_t)(u>>2)*128 + c];
    float4 r; r.x=h0.x+hb.x; r.y=h0.y+hb.y; r.z=h0.z+hb.z; r.w=h0.w+hb.w;
    ((float4*)(out + OFF_UR))[idx] = r;
}

__global__ void k_brepr(float* __restrict__ out)
{
    int idx = blockIdx.x*blockDim.x + threadIdx.x;    // NB*128 float4
    if (idx >= NB*(HID/4)) return;
    ((float4*)(out + OFF_BR))[idx] = ((const float4*)g_h)[idx];
}

// ---------------- launch ----------------
extern "C" void kernel_launch(void* const* d_in, const int* in_sizes, int n_in,
                              void* d_out, int out_size)
{
    const float* Z         = (const float*)d_in[0];
    const int*   B         = (const int*)  d_in[1];
    const int*   A         = (const int*)  d_in[2];
    const int*   AP        = (const int*)  d_in[3];
    const int*   seg       = (const int*)  d_in[6];
    const float* noise     = (const float*)d_in[7];
    const int*   nl        = (const int*)  d_in[8];
    const float* sigmas    = (const float*)d_in[9];
    const float* atom_emb  = (const float*)d_in[10];
    const float* pos_emb   = (const float*)d_in[11];
    const float* block_emb = (const float*)d_in[12];
    const float* edge_emb  = (const float*)d_in[13];
    const float* Wm        = (const float*)d_in[14];
    const float* We        = (const float*)d_in[15];
    const float* Wu        = (const float*)d_in[16];
    const float* wz        = (const float*)d_in[17];
    const float* W1        = (const float*)d_in[18];
    const float* b1        = (const float*)d_in[19];
    const float* W2        = (const float*)d_in[20];
    float* out = (float*)d_out;

    float *p_h, *p_hW, *p_agg, *p_t, *p_ZbA, *p_ZbB, *p_eW;
    cudaGetSymbolAddress((void**)&p_h,   g_h);
    cudaGetSymbolAddress((void**)&p_hW,  g_hW);
    cudaGetSymbolAddress((void**)&p_agg, g_agg);
    cudaGetSymbolAddress((void**)&p_t,   g_t);
    cudaGetSymbolAddress((void**)&p_ZbA, g_ZbA);
    cudaGetSymbolAddress((void**)&p_ZbB, g_ZbB);
    cudaGetSymbolAddress((void**)&p_eW,  g_eW);

    k_perturb<<<(NU+255)/256, 256>>>(Z, noise, nl, sigmas);
    k_zb0<<<(NB+255)/256, 256>>>();
    k_H0<<<(NU*(HID/4)+255)/256, 256>>>(A, AP, B, atom_emb, pos_emb, block_emb);
    k_hinit<<<(NB*(HID/4)+255)/256, 256>>>();
    k_ew<<<(LAY*2*HID+255)/256, 256>>>(edge_emb, We);

    cudaFuncSetAttribute(k_knn, cudaFuncAttributeMaxDynamicSharedMemorySize, KNN_SMEM);
    k_knn<<<dim3(4, G), 256, KNN_SMEM>>>(seg);

    float* zold = p_ZbA;
    float* znew = p_ZbB;
    for (int l = 0; l < LAY; l++) {
        sgemm_k<0,0><<<dim3(4,64), 256>>>(p_h, Wm + (size_t)l*HID*HID, p_hW, nullptr, nullptr);
        k_edge<<<NB, 128>>>(wz + l*HID, p_eW + l*2*HID, zold, znew);
        sgemm_k<0,1><<<dim3(4,64), 256>>>(p_agg, Wu + (size_t)l*HID*HID, p_h, p_h, nullptr);
        float* tmp = zold; zold = znew; znew = tmp;
    }
    // after 3 swaps the final Zb lives in g_ZbB (A->B, B->A, A->B)

    sgemm_k<1,2><<<dim3(4,64), 256>>>(p_h, W1, p_t, nullptr, b1);
    k_eblk<<<NB, 128>>>(W2);
    k_energy<<<G, 256>>>(out);
    k_graph<<<G, 512>>>(out);
    k_noise_loss<<<(NU+255)/256, 256>>>(noise, out);
    k_unit<<<(NU*(HID/4)+255)/256, 256>>>(out);
    k_brepr<<<(NB*(HID/4)+255)/256, 256>>>(out);
}

// round 8
// speedup vs baseline: 2.2737x; 2.2737x over previous
#include <cuda_runtime.h>
#include <math.h>
#include <stdint.h>

#define G    8
#define NBG  1024
#define APB  4
#define HID  512
#define ES   64
#define KNN  9
#define LAY  3
#define NB   (G*NBG)        // 8192
#define NU   (NB*APB)       // 32768
#define NE   (2*KNN)        // 18 edges per dst block
#define JP   4              // knn j-partitions

// output layout (float32, concatenated reference outputs)
#define OFF_E    0
#define OFF_PN   8
#define OFF_UR   98312            // 8 + 32768*3
#define OFF_BR   16875528         // + 32768*512
#define OFF_GR   21069832         // + 8192*512
#define OFF_LOSS 21073928         // + 8*512

// ---------------- scratch (static device globals; no allocations) ----------
__device__ float4 g_ZpS[NU];          // x,y,z,sq
__device__ float  g_H0[NU*HID];       // 64 MB
__device__ float  g_h[NB*HID];
__device__ float  g_hW[NB*HID];
__device__ float  g_agg[NB*HID];
__device__ float  g_t[NB*HID];
__device__ float  g_Zb0[NB*3];
__device__ float  g_ZbA[NB*3];
__device__ float  g_ZbB[NB*3];
__device__ int    g_nbr[NB*NE];
__device__ float  g_eW[LAY*2*HID];
__device__ float  g_eblk[NB];
__device__ float  g_pD[NB*JP*2*KNN];  // partial knn distances
__device__ int    g_pI[NB*JP*2*KNN];  // partial knn indices (graph-local)

__device__ __forceinline__ float silu_f(float x){ return x / (1.0f + expf(-x)); }

// ---------------- 1. perturb + sq ----------------
__global__ void k_perturb(const float* __restrict__ Z, const float* __restrict__ noise,
                          const int* __restrict__ nl, const float* __restrict__ sigmas)
{
    int u = blockIdx.x*blockDim.x + threadIdx.x;
    if (u >= NU) return;
    int g = u >> 12;
    float s = sigmas[nl[g]];
    float x = Z[u*3+0] + noise[u*3+0]*s;
    float y = Z[u*3+1] + noise[u*3+1]*s;
    float z = Z[u*3+2] + noise[u*3+2]*s;
    float4 v; v.x=x; v.y=y; v.z=z; v.w = x*x + y*y + z*z;
    g_ZpS[u] = v;
}

// ---------------- 2. block coordinate means ----------------
__global__ void k_zb0()
{
    int b = blockIdx.x*blockDim.x + threadIdx.x;
    if (b >= NB) return;
    float4 a0 = g_ZpS[b*4+0], a1 = g_ZpS[b*4+1], a2 = g_ZpS[b*4+2], a3 = g_ZpS[b*4+3];
    float x = (((a0.x+a1.x)+a2.x)+a3.x)*0.25f;
    float y = (((a0.y+a1.y)+a2.y)+a3.y)*0.25f;
    float z = (((a0.z+a1.z)+a2.z)+a3.z)*0.25f;
    g_Zb0[b*3+0]=x; g_Zb0[b*3+1]=y; g_Zb0[b*3+2]=z;
    g_ZbA[b*3+0]=x; g_ZbA[b*3+1]=y; g_ZbA[b*3+2]=z;
}

// ---------------- 3. fused H0 + block mean h ----------------
__global__ __launch_bounds__(128) void k_H0h(const int* __restrict__ A, const int* __restrict__ P,
                     const int* __restrict__ B,
                     const float* __restrict__ ae, const float* __restrict__ pe,
                     const float* __restrict__ be)
{
    int b = blockIdx.x;           // block index
    int c = threadIdx.x;          // float4 channel 0..127
    const float4* ae4 = (const float4*)ae;
    const float4* pe4 = (const float4*)pe;
    const float4* be4 = (const float4*)be;
    float4 bb = be4[B[b]*128 + c];
    float sx=0.f, sy=0.f, sz=0.f, sw=0.f;
    #pragma unroll
    for (int a = 0; a < 4; a++) {
        int u = b*4 + a;
        float4 av = ae4[A[u]*128 + c];
        float4 pv = pe4[P[u]*128 + c];
        float4 r;
        r.x = av.x + pv.x + bb.x;
        r.y = av.y + pv.y + bb.y;
        r.z = av.z + pv.z + bb.z;
        r.w = av.w + pv.w + bb.w;
        ((float4*)g_H0)[(size_t)u*128 + c] = r;
        sx += r.x; sy += r.y; sz += r.z; sw += r.w;
    }
    float4 hm; hm.x = sx*0.25f; hm.y = sy*0.25f; hm.z = sz*0.25f; hm.w = sw*0.25f;
    ((float4*)g_h)[(size_t)b*128 + c] = hm;
}

// ---------------- 4. eW[l][type][c] = edge_emb[type] @ We[l] ----------------
__global__ void k_ew(const float* __restrict__ ee, const float* __restrict__ We)
{
    int idx = blockIdx.x*blockDim.x + threadIdx.x;
    if (idx >= LAY*2*HID) return;
    int l = idx / (2*HID);
    int r = idx % (2*HID);
    int t = r / HID;
    int c = r % HID;
    float acc = 0.f;
    #pragma unroll 8
    for (int k = 0; k < ES; k++)
        acc += ee[t*ES+k] * We[(l*ES+k)*HID + c];
    g_eW[idx] = acc;
}

// ---------------- 5. KNN: partial top-9 over a j-quarter ----------------
__device__ __forceinline__ void ins9(float D, int j, float* bd, int* bi)
{
    if (D >= bd[8]) return;
    int p = 8;
    while (p > 0 && bd[p-1] > D) { bd[p]=bd[p-1]; bi[p]=bi[p-1]; --p; }
    bd[p]=D; bi[p]=j;
}

__device__ __forceinline__ void ins9lex(float D, int i, float* bd, int* bi)
{
    if (D > bd[8] || (D == bd[8] && i >= bi[8])) return;
    int p = 8;
    while (p > 0 && (bd[p-1] > D || (bd[p-1] == D && bi[p-1] > i))) {
        bd[p]=bd[p-1]; bi[p]=bi[p-1]; --p;
    }
    bd[p]=D; bi[p]=i;
}

__global__ __launch_bounds__(256) void k_knn_part(const int* __restrict__ seg)
{
    __shared__ float4 sa[256*APB];          // atoms of this j-quarter
    __shared__ int sseg[256];
    int part  = blockIdx.x;                 // 0..3
    int chunk = blockIdx.y;                 // 0..3 (dst chunk of 256)
    int g     = blockIdx.z;                 // graph
    int jbase = part*256;                   // local block base of this quarter
    int abase = g*NBG*APB + jbase*APB;
    for (int i = threadIdx.x; i < 256*APB; i += 256) sa[i] = g_ZpS[abase + i];
    sseg[threadIdx.x] = seg[g*NBG + jbase + threadIdx.x];
    __syncthreads();

    int ib = chunk*256 + threadIdx.x;       // local dst block
    int gd = g*NBG + ib;                    // global dst block
    float4 o0 = g_ZpS[gd*4+0], o1 = g_ZpS[gd*4+1], o2 = g_ZpS[gd*4+2], o3 = g_ZpS[gd*4+3];
    int myseg = seg[gd];

    float bd0[KNN], bd1[KNN]; int bi0[KNN], bi1[KNN];
    #pragma unroll
    for (int k = 0; k < KNN; k++) { bd0[k]=3.0e38f; bd1[k]=3.0e38f; bi0[k]=0x3fffffff; bi1[k]=0x3fffffff; }

    for (int jj = 0; jj < 256; jj++) {
        float4 c0 = sa[jj*4+0], c1 = sa[jj*4+1], c2 = sa[jj*4+2], c3 = sa[jj*4+3];
        #define DD(o,c) ((o).w + (c).w - 2.0f*((o).x*(c).x + (o).y*(c).y + (o).z*(c).z))
        float d = DD(o0,c0);
        d = fminf(d, DD(o0,c1)); d = fminf(d, DD(o0,c2)); d = fminf(d, DD(o0,c3));
        d = fminf(d, DD(o1,c0)); d = fminf(d, DD(o1,c1)); d = fminf(d, DD(o1,c2)); d = fminf(d, DD(o1,c3));
        d = fminf(d, DD(o2,c0)); d = fminf(d, DD(o2,c1)); d = fminf(d, DD(o2,c2)); d = fminf(d, DD(o2,c3));
        d = fminf(d, DD(o3,c0)); d = fminf(d, DD(o3,c1)); d = fminf(d, DD(o3,c2)); d = fminf(d, DD(o3,c3));
        #undef DD
        int j = jbase + jj;
        if (sseg[jj] == myseg) {
            if (j != ib) ins9(d, j, bd0, bi0);
        } else {
            ins9(d, j, bd1, bi1);
        }
    }
    size_t base = ((size_t)gd*JP + part)*2*KNN;
    #pragma unroll
    for (int k = 0; k < KNN; k++) {
        g_pD[base + k] = bd0[k];          g_pI[base + k] = bi0[k];
        g_pD[base + KNN + k] = bd1[k];    g_pI[base + KNN + k] = bi1[k];
    }
}

__global__ void k_knn_merge()
{
    int b = blockIdx.x*blockDim.x + threadIdx.x;
    if (b >= NB) return;
    int goff = (b >> 10) * NBG;            // graph offset
    #pragma unroll
    for (int list = 0; list < 2; list++) {
        float od[KNN]; int oi[KNN];
        #pragma unroll
        for (int k = 0; k < KNN; k++) { od[k]=3.1e38f; oi[k]=0x7fffffff; }
        for (int part = 0; part < JP; part++) {
            size_t base = ((size_t)b*JP + part)*2*KNN + list*KNN;
            #pragma unroll
            for (int k = 0; k < KNN; k++)
                ins9lex(g_pD[base+k], g_pI[base+k], od, oi);
        }
        #pragma unroll
        for (int k = 0; k < KNN; k++)
            g_nbr[b*NE + list*KNN + k] = goff + oi[k];
    }
}

// ---------------- 6. SGEMM: C[8192,512] = A[8192,512] @ B[512,512] ---------
// EPI 0: C = acc;  EPI 1: C = addC + silu(acc);  EPI 2: C = acc + bias[col]
// 128x128 tile, 256 threads, 8x8 frags, 16-deep k-panel, double buffered.
template<int EPI>
__global__ __launch_bounds__(256,2) void sgemm_k(
    const float* __restrict__ A, const float* __restrict__ Bm,
    float* __restrict__ C, const float* __restrict__ addC,
    const float* __restrict__ bias)
{
    __shared__ float As[2][16][128];
    __shared__ float Bs[2][16][128];
    const int tid  = threadIdx.x;
    const int brow = blockIdx.y * 128;
    const int bcol = blockIdx.x * 128;
    const int ty = tid >> 4, tx = tid & 15;
    const int ar0 = tid >> 2;             // A row 0..63 (+64 on 2nd iter)
    const int akc = (tid & 3) << 2;       // A k quad: 0,4,8,12
    const int bkr0 = tid >> 5;            // B k row 0..7 (+8 on 2nd iter)
    const int bc  = (tid & 31) << 2;      // B col quad

    // prologue: panel 0 straight to smem
    #pragma unroll
    for (int i = 0; i < 2; i++) {
        int r = ar0 + i*64;
        float4 v = *(const float4*)(A + (size_t)(brow+r)*HID + akc);
        As[0][akc+0][r]=v.x; As[0][akc+1][r]=v.y; As[0][akc+2][r]=v.z; As[0][akc+3][r]=v.w;
        int kr = bkr0 + i*8;
        *(float4*)&Bs[0][kr][bc] = *(const float4*)(Bm + (size_t)kr*HID + bcol + bc);
    }
    __syncthreads();

    float acc[8][8];
    #pragma unroll
    for (int i = 0; i < 8; i++) {
        #pragma unroll
        for (int j = 0; j < 8; j++) acc[i][j] = 0.f;
    }

    float4 a_reg[2], b_reg[2];
    for (int p = 0; p < 32; p++) {
        int buf = p & 1;
        if (p < 31) {
            int kp = (p+1)*16;
            #pragma unroll
            for (int i = 0; i < 2; i++) {
                a_reg[i] = *(const float4*)(A + (size_t)(brow+ar0+i*64)*HID + kp + akc);
                b_reg[i] = *(const float4*)(Bm + (size_t)(kp+bkr0+i*8)*HID + bcol + bc);
            }
        }
        #pragma unroll
        for (int k = 0; k < 16; k++) {
            float4 a0 = *(const float4*)&As[buf][k][ty*8];
            float4 a1 = *(const float4*)&As[buf][k][ty*8+4];
            float4 b0 = *(const float4*)&Bs[buf][k][tx*8];
            float4 b1 = *(const float4*)&Bs[buf][k][tx*8+4];
            float ar[8] = {a0.x,a0.y,a0.z,a0.w,a1.x,a1.y,a1.z,a1.w};
            float br[8] = {b0.x,b0.y,b0.z,b0.w,b1.x,b1.y,b1.z,b1.w};
            #pragma unroll
            for (int i = 0; i < 8; i++) {
                #pragma unroll
                for (int j = 0; j < 8; j++) acc[i][j] += ar[i]*br[j];
            }
        }
        if (p < 31) {
            int nb = buf ^ 1;
            #pragma unroll
            for (int i = 0; i < 2; i++) {
                int r = ar0 + i*64;
                As[nb][akc+0][r]=a_reg[i].x; As[nb][akc+1][r]=a_reg[i].y;
                As[nb][akc+2][r]=a_reg[i].z; As[nb][akc+3][r]=a_reg[i].w;
                *(float4*)&Bs[nb][bkr0+i*8][bc] = b_reg[i];
            }
        }
        __syncthreads();
    }

    #pragma unroll
    for (int i = 0; i < 8; i++) {
        int row = brow + ty*8 + i;
        #pragma unroll
        for (int j = 0; j < 8; j++) {
            int col = bcol + tx*8 + j;
            float v = acc[i][j];
            if (EPI == 1) v = addC[(size_t)row*HID+col] + silu_f(v);
            if (EPI == 2) v = v + bias[col];
            C[(size_t)row*HID+col] = v;
        }
    }
}

// ---------------- 7. silu pre-pass for energy head ----------------
__global__ void k_silu()
{
    int idx = blockIdx.x*blockDim.x + threadIdx.x;
    if (idx >= NB*(HID/4)) return;
    float4 v = ((const float4*)g_h)[idx];
    v.x = silu_f(v.x); v.y = silu_f(v.y); v.z = silu_f(v.z); v.w = silu_f(v.w);
    ((float4*)g_hW)[idx] = v;
}

// ---------------- 8. fused edge/message kernel ----------------
__global__ __launch_bounds__(128) void k_edge(
    const float* __restrict__ wz_l, const float* __restrict__ eWl,
    const float* __restrict__ Zb_old, float* __restrict__ Zb_new)
{
    int d = blockIdx.x;
    int tid = threadIdx.x;                      // 128 threads, 4 channels each
    const float4* hW4 = (const float4*)g_hW;
    float4 hd  = hW4[(size_t)d*128 + tid];
    float4 wzv = ((const float4*)wz_l)[tid];
    float4 ew0 = ((const float4*)eWl)[tid];
    float4 ew1 = ((const float4*)(eWl + HID))[tid];
    float4 ag = make_float4(0.f,0.f,0.f,0.f);

    __shared__ int   snbr[NE];
    __shared__ float sp[NE][4];
    __shared__ float sx[NE], sy[NE], sz[NE];
    if (tid < NE) snbr[tid] = g_nbr[d*NE + tid];
    __syncthreads();

    int wid = tid >> 5, lane = tid & 31;
    #pragma unroll
    for (int e = 0; e < NE; e++) {
        int s = snbr[e];
        float4 ew = (e < KNN) ? ew0 : ew1;
        float4 hs = hW4[(size_t)s*128 + tid];
        float m0 = silu_f(hs.x + hd.x + ew.x);
        float m1 = silu_f(hs.y + hd.y + ew.y);
        float m2 = silu_f(hs.z + hd.z + ew.z);
        float m3 = silu_f(hs.w + hd.w + ew.w);
        ag.x += m0; ag.y += m1; ag.z += m2; ag.w += m3;
        float p = m0*wzv.x + m1*wzv.y + m2*wzv.z + m3*wzv.w;
        #pragma unroll
        for (int off = 16; off; off >>= 1) p += __shfl_down_sync(0xffffffffu, p, off);
        if (lane == 0) sp[e][wid] = p;
    }
    __syncthreads();

    float Zdx = Zb_old[d*3+0], Zdy = Zb_old[d*3+1], Zdz = Zb_old[d*3+2];
    if (tid < NE) {
        float coef = tanhf(sp[tid][0] + sp[tid][1] + sp[tid][2] + sp[tid][3]);
        int s = snbr[tid];
        sx[tid] = (Zb_old[s*3+0] - Zdx)*coef;
        sy[tid] = (Zb_old[s*3+1] - Zdy)*coef;
        sz[tid] = (Zb_old[s*3+2] - Zdz)*coef;
    }
    __syncthreads();

    ((float4*)g_agg)[(size_t)d*128 + tid] = ag;
    if (tid == 0) {
        float zx=0.f, zy=0.f, zz=0.f;
        #pragma unroll
        for (int e = 0; e < NE; e++) { zx += sx[e]; zy += sy[e]; zz += sz[e]; }
        const float inv = 1.0f / (2*KNN);
        Zb_new[d*3+0] = Zdx + zx*inv;
        Zb_new[d*3+1] = Zdy + zy*inv;
        Zb_new[d*3+2] = Zdz + zz*inv;
    }
}

// ---------------- 9. energy head ----------------
__global__ __launch_bounds__(128) void k_eblk(const float* __restrict__ W2)
{
    int b = blockIdx.x;
    int tid = threadIdx.x;
    float4 tv = ((const float4*)g_t)[(size_t)b*128 + tid];
    float4 w  = ((const float4*)W2)[tid];
    float p = silu_f(tv.x)*w.x + silu_f(tv.y)*w.y + silu_f(tv.z)*w.z + silu_f(tv.w)*w.w;
    __shared__ float sred[4];
    #pragma unroll
    for (int off = 16; off; off >>= 1) p += __shfl_down_sync(0xffffffffu, p, off);
    if ((tid & 31) == 0) sred[tid >> 5] = p;
    __syncthreads();
    if (tid == 0) g_eblk[b] = sred[0]+sred[1]+sred[2]+sred[3];
}

__global__ __launch_bounds__(256) void k_energy(float* __restrict__ out)
{
    int g = blockIdx.x;
    int tid = threadIdx.x;
    float p = 0.f;
    #pragma unroll
    for (int k = 0; k < 4; k++) p += g_eblk[g*NBG + k*256 + tid];
    __shared__ float sred[8];
    #pragma unroll
    for (int off = 16; off; off >>= 1) p += __shfl_down_sync(0xffffffffu, p, off);
    if ((tid & 31) == 0) sred[tid >> 5] = p;
    __syncthreads();
    if (tid == 0) {
        float s = 0.f;
        #pragma unroll
        for (int w = 0; w < 8; w++) s += sred[w];
        out[OFF_E + g] = s;
        if (g == 0) out[OFF_LOSS] = 0.f;     // zero loss accumulator (runs before k_noise_loss)
    }
}

// ---------------- 10. graph_repr ----------------
__global__ __launch_bounds__(512) void k_graph(float* __restrict__ out)
{
    int g = blockIdx.x;
    int tid = threadIdx.x;       // channel
    float acc = 0.f;
    const float* hp = g_h + (size_t)g*NBG*HID + tid;
    for (int b = 0; b < NBG; b++) acc += hp[(size_t)b*HID];
    out[OFF_GR + g*HID + tid] = acc;
}

// ---------------- 11. pred_noise + loss ----------------
__global__ __launch_bounds__(256) void k_noise_loss(const float* __restrict__ noise,
                                                    float* __restrict__ out)
{
    int u = blockIdx.x*blockDim.x + threadIdx.x;
    float local = 0.f;
    if (u < NU) {
        int b = u >> 2;
        float dx = g_ZbB[b*3+0] - g_Zb0[b*3+0];
        float dy = g_ZbB[b*3+1] - g_Zb0[b*3+1];
        float dz = g_ZbB[b*3+2] - g_Zb0[b*3+2];
        out[OFF_PN + u*3+0] = dx;
        out[OFF_PN + u*3+1] = dy;
        out[OFF_PN + u*3+2] = dz;
        float ex = dx - noise[u*3+0];
        float ey = dy - noise[u*3+1];
        float ez = dz - noise[u*3+2];
        local = ex*ex + ey*ey + ez*ez;
    }
    __shared__ float sred[8];
    float p = local;
    #pragma unroll
    for (int off = 16; off; off >>= 1) p += __shfl_down_sync(0xffffffffu, p, off);
    if ((threadIdx.x & 31) == 0) sred[threadIdx.x >> 5] = p;
    __syncthreads();
    if (threadIdx.x == 0) {
        float s = 0.f;
        #pragma unroll
        for (int w = 0; w < 8; w++) s += sred[w];
        atomicAdd(out + OFF_LOSS, s * 0.0625f);   // 0.5/G
    }
}

// ---------------- 12. unit_repr & block_repr ----------------
__global__ void k_unit(float* __restrict__ out)
{
    int idx = blockIdx.x*blockDim.x + threadIdx.x;    // NU*128 float4
    if (idx >= NU*(HID/4)) return;
    int u = idx >> 7;
    int c = idx & 127;
    float4 h0 = ((const float4*)g_H0)[idx];
    float4 hb = ((const float4*)g_h)[(size_t)(u>>2)*128 + c];
    float4 r; r.x=h0.x+hb.x; r.y=h0.y+hb.y; r.z=h0.z+hb.z; r.w=h0.w+hb.w;
    ((float4*)(out + OFF_UR))[idx] = r;
}

__global__ void k_brepr(float* __restrict__ out)
{
    int idx = blockIdx.x*blockDim.x + threadIdx.x;    // NB*128 float4
    if (idx >= NB*(HID/4)) return;
    ((float4*)(out + OFF_BR))[idx] = ((const float4*)g_h)[idx];
}

// ---------------- launch ----------------
extern "C" void kernel_launch(void* const* d_in, const int* in_sizes, int n_in,
                              void* d_out, int out_size)
{
    const float* Z         = (const float*)d_in[0];
    const int*   B         = (const int*)  d_in[1];
    const int*   A         = (const int*)  d_in[2];
    const int*   AP        = (const int*)  d_in[3];
    const int*   seg       = (const int*)  d_in[6];
    const float* noise     = (const float*)d_in[7];
    const int*   nl        = (const int*)  d_in[8];
    const float* sigmas    = (const float*)d_in[9];
    const float* atom_emb  = (const float*)d_in[10];
    const float* pos_emb   = (const float*)d_in[11];
    const float* block_emb = (const float*)d_in[12];
    const float* edge_emb  = (const float*)d_in[13];
    const float* Wm        = (const float*)d_in[14];
    const float* We        = (const float*)d_in[15];
    const float* Wu        = (const float*)d_in[16];
    const float* wz        = (const float*)d_in[17];
    const float* W1        = (const float*)d_in[18];
    const float* b1        = (const float*)d_in[19];
    const float* W2        = (const float*)d_in[20];
    float* out = (float*)d_out;

    float *p_h, *p_hW, *p_agg, *p_t, *p_ZbA, *p_ZbB, *p_eW;
    cudaGetSymbolAddress((void**)&p_h,   g_h);
    cudaGetSymbolAddress((void**)&p_hW,  g_hW);
    cudaGetSymbolAddress((void**)&p_agg, g_agg);
    cudaGetSymbolAddress((void**)&p_t,   g_t);
    cudaGetSymbolAddress((void**)&p_ZbA, g_ZbA);
    cudaGetSymbolAddress((void**)&p_ZbB, g_ZbB);
    cudaGetSymbolAddress((void**)&p_eW,  g_eW);

    k_perturb<<<(NU+255)/256, 256>>>(Z, noise, nl, sigmas);
    k_zb0<<<(NB+255)/256, 256>>>();
    k_H0h<<<NB, 128>>>(A, AP, B, atom_emb, pos_emb, block_emb);
    k_ew<<<(LAY*2*HID+255)/256, 256>>>(edge_emb, We);

    k_knn_part<<<dim3(JP, 4, G), 256>>>(seg);
    k_knn_merge<<<(NB+255)/256, 256>>>();

    float* zold = p_ZbA;
    float* znew = p_ZbB;
    for (int l = 0; l < LAY; l++) {
        sgemm_k<0><<<dim3(4,64), 256>>>(p_h, Wm + (size_t)l*HID*HID, p_hW, nullptr, nullptr);
        k_edge<<<NB, 128>>>(wz + l*HID, p_eW + l*2*HID, zold, znew);
        sgemm_k<1><<<dim3(4,64), 256>>>(p_agg, Wu + (size_t)l*HID*HID, p_h, p_h, nullptr);
        float* tmp = zold; zold = znew; znew = tmp;
    }
    // after 3 swaps the final Zb lives in g_ZbB (A->B, B->A, A->B)

    k_silu<<<(NB*(HID/4)+255)/256, 256>>>();
    sgemm_k<2><<<dim3(4,64), 256>>>(p_hW, W1, p_t, nullptr, b1);
    k_eblk<<<NB, 128>>>(W2);
    k_energy<<<G, 256>>>(out);
    k_graph<<<G, 512>>>(out);
    k_noise_loss<<<(NU+255)/256, 256>>>(noise, out);
    k_unit<<<(NU*(HID/4)+255)/256, 256>>>(out);
    k_brepr<<<(NB*(HID/4)+255)/256, 256>>>(out);
}

// round 10
// speedup vs baseline: 2.7859x; 1.2253x over previous
#include <cuda_runtime.h>
#include <math.h>
#include <stdint.h>

#define G    8
#define NBG  1024
#define APB  4
#define HID  512
#define ES   64
#define KNN  9
#define LAY  3
#define NB   (G*NBG)        // 8192
#define NU   (NB*APB)       // 32768
#define NE   (2*KNN)        // 18 edges per dst block
#define JP   4              // knn j-partitions

// output layout (float32, concatenated reference outputs)
#define OFF_E    0
#define OFF_PN   8
#define OFF_UR   98312            // 8 + 32768*3
#define OFF_BR   16875528         // + 32768*512
#define OFF_GR   21069832         // + 8192*512
#define OFF_LOSS 21073928         // + 8*512

// ---------------- scratch (static device globals; no allocations) ----------
__device__ float4 g_ZpS[NU];          // x,y,z,sq
__device__ float  g_H0[NU*HID];       // 64 MB
__device__ float  g_h[NB*HID];
__device__ float  g_hW[NB*HID];
__device__ float  g_agg[NB*HID];
__device__ float  g_t[NB*HID];
__device__ float  g_Zb0[NB*3];
__device__ float  g_ZbA[NB*3];
__device__ float  g_ZbB[NB*3];
__device__ int    g_nbr[NB*NE];
__device__ float  g_eW[LAY*2*HID];
__device__ float  g_eblk[NB];
__device__ float  g_pD[NB*JP*2*KNN];  // partial knn distances
__device__ int    g_pI[NB*JP*2*KNN];  // partial knn indices (graph-local)

__device__ __forceinline__ float silu_f(float x){ return x / (1.0f + expf(-x)); }

__device__ __forceinline__ uint32_t f2tf32(float f){
    uint32_t u;
    asm("cvt.rna.tf32.f32 %0, %1;" : "=r"(u) : "f"(f));
    return u;
}

__device__ __forceinline__ void mma_tf32(float* d, const uint32_t* a, const uint32_t* b){
    asm volatile("mma.sync.aligned.m16n8k8.row.col.f32.tf32.tf32.f32 "
        "{%0,%1,%2,%3}, {%4,%5,%6,%7}, {%8,%9}, {%0,%1,%2,%3};"
        : "+f"(d[0]), "+f"(d[1]), "+f"(d[2]), "+f"(d[3])
        : "r"(a[0]), "r"(a[1]), "r"(a[2]), "r"(a[3]), "r"(b[0]), "r"(b[1]));
}

// ---------------- 1. perturb + sq ----------------
__global__ void k_perturb(const float* __restrict__ Z, const float* __restrict__ noise,
                          const int* __restrict__ nl, const float* __restrict__ sigmas)
{
    int u = blockIdx.x*blockDim.x + threadIdx.x;
    if (u >= NU) return;
    int g = u >> 12;
    float s = sigmas[nl[g]];
    float x = Z[u*3+0] + noise[u*3+0]*s;
    float y = Z[u*3+1] + noise[u*3+1]*s;
    float z = Z[u*3+2] + noise[u*3+2]*s;
    float4 v; v.x=x; v.y=y; v.z=z; v.w = x*x + y*y + z*z;
    g_ZpS[u] = v;
}

// ---------------- 2. block coordinate means ----------------
__global__ void k_zb0()
{
    int b = blockIdx.x*blockDim.x + threadIdx.x;
    if (b >= NB) return;
    float4 a0 = g_ZpS[b*4+0], a1 = g_ZpS[b*4+1], a2 = g_ZpS[b*4+2], a3 = g_ZpS[b*4+3];
    float x = (((a0.x+a1.x)+a2.x)+a3.x)*0.25f;
    float y = (((a0.y+a1.y)+a2.y)+a3.y)*0.25f;
    float z = (((a0.z+a1.z)+a2.z)+a3.z)*0.25f;
    g_Zb0[b*3+0]=x; g_Zb0[b*3+1]=y; g_Zb0[b*3+2]=z;
    g_ZbA[b*3+0]=x; g_ZbA[b*3+1]=y; g_ZbA[b*3+2]=z;
}

// ---------------- 3. fused H0 + block mean h ----------------
__global__ __launch_bounds__(128) void k_H0h(const int* __restrict__ A, const int* __restrict__ P,
                     const int* __restrict__ B,
                     const float* __restrict__ ae, const float* __restrict__ pe,
                     const float* __restrict__ be)
{
    int b = blockIdx.x;           // block index
    int c = threadIdx.x;          // float4 channel 0..127
    const float4* ae4 = (const float4*)ae;
    const float4* pe4 = (const float4*)pe;
    const float4* be4 = (const float4*)be;
    float4 bb = be4[B[b]*128 + c];
    float sx=0.f, sy=0.f, sz=0.f, sw=0.f;
    #pragma unroll
    for (int a = 0; a < 4; a++) {
        int u = b*4 + a;
        float4 av = ae4[A[u]*128 + c];
        float4 pv = pe4[P[u]*128 + c];
        float4 r;
        r.x = av.x + pv.x + bb.x;
        r.y = av.y + pv.y + bb.y;
        r.z = av.z + pv.z + bb.z;
        r.w = av.w + pv.w + bb.w;
        ((float4*)g_H0)[(size_t)u*128 + c] = r;
        sx += r.x; sy += r.y; sz += r.z; sw += r.w;
    }
    float4 hm; hm.x = sx*0.25f; hm.y = sy*0.25f; hm.z = sz*0.25f; hm.w = sw*0.25f;
    ((float4*)g_h)[(size_t)b*128 + c] = hm;
}

// ---------------- 4. eW[l][type][c] = edge_emb[type] @ We[l] ----------------
__global__ void k_ew(const float* __restrict__ ee, const float* __restrict__ We)
{
    int idx = blockIdx.x*blockDim.x + threadIdx.x;
    if (idx >= LAY*2*HID) return;
    int l = idx / (2*HID);
    int r = idx % (2*HID);
    int t = r / HID;
    int c = r % HID;
    float acc = 0.f;
    #pragma unroll 8
    for (int k = 0; k < ES; k++)
        acc += ee[t*ES+k] * We[(l*ES+k)*HID + c];
    g_eW[idx] = acc;
}

// ---------------- 5. KNN: partial top-9 over a j-quarter ----------------
__device__ __forceinline__ void ins9(float D, int j, float* bd, int* bi)
{
    if (D >= bd[8]) return;
    int p = 8;
    while (p > 0 && bd[p-1] > D) { bd[p]=bd[p-1]; bi[p]=bi[p-1]; --p; }
    bd[p]=D; bi[p]=j;
}

__device__ __forceinline__ void ins9lex(float D, int i, float* bd, int* bi)
{
    if (D > bd[8] || (D == bd[8] && i >= bi[8])) return;
    int p = 8;
    while (p > 0 && (bd[p-1] > D || (bd[p-1] == D && bi[p-1] > i))) {
        bd[p]=bd[p-1]; bi[p]=bi[p-1]; --p;
    }
    bd[p]=D; bi[p]=i;
}

__global__ __launch_bounds__(256) void k_knn_part(const int* __restrict__ seg)
{
    __shared__ float4 sa[256*APB];          // atoms of this j-quarter
    __shared__ int sseg[256];
    int part  = blockIdx.x;                 // 0..3
    int chunk = blockIdx.y;                 // 0..3 (dst chunk of 256)
    int g     = blockIdx.z;                 // graph
    int jbase = part*256;                   // local block base of this quarter
    int abase = g*NBG*APB + jbase*APB;
    for (int i = threadIdx.x; i < 256*APB; i += 256) sa[i] = g_ZpS[abase + i];
    sseg[threadIdx.x] = seg[g*NBG + jbase + threadIdx.x];
    __syncthreads();

    int ib = chunk*256 + threadIdx.x;       // local dst block
    int gd = g*NBG + ib;                    // global dst block
    float4 o0 = g_ZpS[gd*4+0], o1 = g_ZpS[gd*4+1], o2 = g_ZpS[gd*4+2], o3 = g_ZpS[gd*4+3];
    int myseg = seg[gd];

    float bd0[KNN], bd1[KNN]; int bi0[KNN], bi1[KNN];
    #pragma unroll
    for (int k = 0; k < KNN; k++) { bd0[k]=3.0e38f; bd1[k]=3.0e38f; bi0[k]=0x3fffffff; bi1[k]=0x3fffffff; }

    for (int jj = 0; jj < 256; jj++) {
        float4 c0 = sa[jj*4+0], c1 = sa[jj*4+1], c2 = sa[jj*4+2], c3 = sa[jj*4+3];
        #define DD(o,c) ((o).w + (c).w - 2.0f*((o).x*(c).x + (o).y*(c).y + (o).z*(c).z))
        float d = DD(o0,c0);
        d = fminf(d, DD(o0,c1)); d = fminf(d, DD(o0,c2)); d = fminf(d, DD(o0,c3));
        d = fminf(d, DD(o1,c0)); d = fminf(d, DD(o1,c1)); d = fminf(d, DD(o1,c2)); d = fminf(d, DD(o1,c3));
        d = fminf(d, DD(o2,c0)); d = fminf(d, DD(o2,c1)); d = fminf(d, DD(o2,c2)); d = fminf(d, DD(o2,c3));
        d = fminf(d, DD(o3,c0)); d = fminf(d, DD(o3,c1)); d = fminf(d, DD(o3,c2)); d = fminf(d, DD(o3,c3));
        #undef DD
        int j = jbase + jj;
        if (sseg[jj] == myseg) {
            if (j != ib) ins9(d, j, bd0, bi0);
        } else {
            ins9(d, j, bd1, bi1);
        }
    }
    size_t base = ((size_t)gd*JP + part)*2*KNN;
    #pragma unroll
    for (int k = 0; k < KNN; k++) {
        g_pD[base + k] = bd0[k];          g_pI[base + k] = bi0[k];
        g_pD[base + KNN + k] = bd1[k];    g_pI[base + KNN + k] = bi1[k];
    }
}

__global__ void k_knn_merge()
{
    int b = blockIdx.x*blockDim.x + threadIdx.x;
    if (b >= NB) return;
    int goff = (b >> 10) * NBG;            // graph offset
    #pragma unroll
    for (int list = 0; list < 2; list++) {
        float od[KNN]; int oi[KNN];
        #pragma unroll
        for (int k = 0; k < KNN; k++) { od[k]=3.1e38f; oi[k]=0x7fffffff; }
        for (int part = 0; part < JP; part++) {
            size_t base = ((size_t)b*JP + part)*2*KNN + list*KNN;
            #pragma unroll
            for (int k = 0; k < KNN; k++)
                ins9lex(g_pD[base+k], g_pI[base+k], od, oi);
        }
        #pragma unroll
        for (int k = 0; k < KNN; k++)
            g_nbr[b*NE + list*KNN + k] = goff + oi[k];
    }
}

// ---------------- 6. TF32 tensor-core GEMM -------------------------------
// C[8192,512] = op(A)[8192,512] @ B[512,512]
// EPI 0: C = acc;  EPI 1: C = addC + silu(acc);  EPI 2: C = acc + bias[col]
// SILU_A: apply silu to A elements during staging.
// 128x128 CTA tile, 8 warps (2x4), warp tile 64x32, BK=16, double buffered.
// Smem holds tf32 fragments in mma lane order: one LDS.128 / LDS.64 per frag.
template<int SILU_A, int EPI>
__global__ __launch_bounds__(256,2) void sgemm_tc(
    const float* __restrict__ A, const float* __restrict__ Bm,
    float* __restrict__ C, const float* __restrict__ addC,
    const float* __restrict__ bias)
{
    __shared__ uint32_t As[2][2][8][32][4];   // [buf][k8][mtile][lane][slot]
    __shared__ uint32_t Bs[2][2][16][32][2];  // [buf][k8][ntile][lane][slot]
    const int tid  = threadIdx.x;
    const int lane = tid & 31, wid = tid >> 5;
    const int wm = wid >> 2, wn = wid & 3;        // warp grid 2(M) x 4(N)
    const int brow = blockIdx.y*128, bcol = blockIdx.x*128;
    const int gg = lane >> 2, tt = lane & 3;
    const int qa = tid*2;

    float acc[4][4][4];
    #pragma unroll
    for (int mt=0;mt<4;mt++){
        #pragma unroll
        for (int nt=0;nt<4;nt++){
            #pragma unroll
            for (int r=0;r<4;r++) acc[mt][nt][r]=0.f;
        }
    }

    auto loadA = [&](int q, int kp)->float4 {
        int r = q >> 2, cq = q & 3;
        return *(const float4*)(A + (size_t)(brow+r)*HID + kp + 4*cq);
    };
    auto loadB = [&](int q, int kp)->float4 {
        int kb = q >> 5, cq = q & 31;
        return *(const float4*)(Bm + (size_t)(kp+kb)*HID + bcol + 4*cq);
    };
    auto stageA = [&](int buf, float4 v, int q){
        int r = q >> 2, cq = q & 3;
        int mt = r >> 4, rr = r & 15, g2 = rr & 7, rh = rr >> 3;
        float vv[4] = {v.x, v.y, v.z, v.w};
        #pragma unroll
        for (int j=0;j<4;j++){
            int kc = 4*cq + j, ks = kc >> 3, ck = kc & 7, tl = ck & 3, ch = ck >> 2;
            float f = SILU_A ? silu_f(vv[j]) : vv[j];
            As[buf][ks][mt][g2*4+tl][rh + 2*ch] = f2tf32(f);
        }
    };
    auto stageB = [&](int buf, float4 v, int q){
        int kb = q >> 5, cq = q & 31;
        int ks = kb >> 3, kk = kb & 7, tl = kk & 3, s = kk >> 2;
        float vv[4] = {v.x, v.y, v.z, v.w};
        #pragma unroll
        for (int j=0;j<4;j++){
            int nl = 4*cq + j, nt = nl >> 3, nn = nl & 7;
            Bs[buf][ks][nt][nn*4+tl][s] = f2tf32(vv[j]);
        }
    };

    // prologue: panel 0
    stageA(0, loadA(qa,0), qa);   stageA(0, loadA(qa+1,0), qa+1);
    stageB(0, loadB(qa,0), qa);   stageB(0, loadB(qa+1,0), qa+1);
    __syncthreads();

    float4 pa0, pa1, pb0, pb1;
    for (int p = 0; p < 32; p++) {
        int buf = p & 1;
        if (p < 31) {
            int kp = (p+1)*16;
            pa0 = loadA(qa,kp);   pa1 = loadA(qa+1,kp);
            pb0 = loadB(qa,kp);   pb1 = loadB(qa+1,kp);
        }
        #pragma unroll
        for (int ks = 0; ks < 2; ks++) {
            uint32_t af[4][4], bf[4][2];
            #pragma unroll
            for (int mt=0;mt<4;mt++)
                *(uint4*)af[mt] = *(const uint4*)&As[buf][ks][wm*4+mt][lane][0];
            #pragma unroll
            for (int nt=0;nt<4;nt++)
                *(uint2*)bf[nt] = *(const uint2*)&Bs[buf][ks][wn*4+nt][lane][0];
            #pragma unroll
            for (int mt=0;mt<4;mt++){
                #pragma unroll
                for (int nt=0;nt<4;nt++)
                    mma_tf32(acc[mt][nt], af[mt], bf[nt]);
            }
        }
        if (p < 31) {
            int nb = buf ^ 1;
            stageA(nb, pa0, qa);   stageA(nb, pa1, qa+1);
            stageB(nb, pb0, qa);   stageB(nb, pb1, qa+1);
        }
        __syncthreads();
    }

    // epilogue
    #pragma unroll
    for (int mt=0;mt<4;mt++){
        int row0 = brow + wm*64 + mt*16 + gg;
        int row1 = row0 + 8;
        #pragma unroll
        for (int nt=0;nt<4;nt++){
            int col = bcol + wn*32 + nt*8 + 2*tt;
            float v0 = acc[mt][nt][0], v1 = acc[mt][nt][1];
            float v2 = acc[mt][nt][2], v3 = acc[mt][nt][3];
            if (EPI == 1) {
                float2 c0 = *(const float2*)(addC + (size_t)row0*HID + col);
                float2 c1 = *(const float2*)(addC + (size_t)row1*HID + col);
                v0 = c0.x + silu_f(v0); v1 = c0.y + silu_f(v1);
                v2 = c1.x + silu_f(v2); v3 = c1.y + silu_f(v3);
            }
            if (EPI == 2) {
                float2 bb = *(const float2*)(bias + col);
                v0 += bb.x; v1 += bb.y; v2 += bb.x; v3 += bb.y;
            }
            float2 o0; o0.x=v0; o0.y=v1;
            float2 o1; o1.x=v2; o1.y=v3;
            *(float2*)(C + (size_t)row0*HID + col) = o0;
            *(float2*)(C + (size_t)row1*HID + col) = o1;
        }
    }
}

// ---------------- 7. fused edge/message kernel ----------------
__global__ __launch_bounds__(128) void k_edge(
    const float* __restrict__ wz_l, const float* __restrict__ eWl,
    const float* __restrict__ Zb_old, float* __restrict__ Zb_new)
{
    int d = blockIdx.x;
    int tid = threadIdx.x;                      // 128 threads, 4 channels each
    const float4* hW4 = (const float4*)g_hW;
    float4 hd  = hW4[(size_t)d*128 + tid];
    float4 wzv = ((const float4*)wz_l)[tid];
    float4 ew0 = ((const float4*)eWl)[tid];
    float4 ew1 = ((const float4*)(eWl + HID))[tid];
    float4 ag = make_float4(0.f,0.f,0.f,0.f);

    __shared__ int   snbr[NE];
    __shared__ float sp[NE][4];
    __shared__ float sx[NE], sy[NE], sz[NE];
    if (tid < NE) snbr[tid] = g_nbr[d*NE + tid];
    __syncthreads();

    int wid = tid >> 5, lane = tid & 31;
    #pragma unroll
    for (int e = 0; e < NE; e++) {
        int s = snbr[e];
        float4 ew = (e < KNN) ? ew0 : ew1;
        float4 hs = hW4[(size_t)s*128 + tid];
        float m0 = silu_f(hs.x + hd.x + ew.x);
        float m1 = silu_f(hs.y + hd.y + ew.y);
        float m2 = silu_f(hs.z + hd.z + ew.z);
        float m3 = silu_f(hs.w + hd.w + ew.w);
        ag.x += m0; ag.y += m1; ag.z += m2; ag.w += m3;
        float p = m0*wzv.x + m1*wzv.y + m2*wzv.z + m3*wzv.w;
        #pragma unroll
        for (int off = 16; off; off >>= 1) p += __shfl_down_sync(0xffffffffu, p, off);
        if (lane == 0) sp[e][wid] = p;
    }
    __syncthreads();

    float Zdx = Zb_old[d*3+0], Zdy = Zb_old[d*3+1], Zdz = Zb_old[d*3+2];
    if (tid < NE) {
        float coef = tanhf(sp[tid][0] + sp[tid][1] + sp[tid][2] + sp[tid][3]);
        int s = snbr[tid];
        sx[tid] = (Zb_old[s*3+0] - Zdx)*coef;
        sy[tid] = (Zb_old[s*3+1] - Zdy)*coef;
        sz[tid] = (Zb_old[s*3+2] - Zdz)*coef;
    }
    __syncthreads();

    ((float4*)g_agg)[(size_t)d*128 + tid] = ag;
    if (tid == 0) {
        float zx=0.f, zy=0.f, zz=0.f;
        #pragma unroll
        for (int e = 0; e < NE; e++) { zx += sx[e]; zy += sy[e]; zz += sz[e]; }
        const float inv = 1.0f / (2*KNN);
        Zb_new[d*3+0] = Zdx + zx*inv;
        Zb_new[d*3+1] = Zdy + zy*inv;
        Zb_new[d*3+2] = Zdz + zz*inv;
    }
}

// ---------------- 8. energy head ----------------
__global__ __launch_bounds__(128) void k_eblk(const float* __restrict__ W2)
{
    int b = blockIdx.x;
    int tid = threadIdx.x;
    float4 tv = ((const float4*)g_t)[(size_t)b*128 + tid];
    float4 w  = ((const float4*)W2)[tid];
    float p = silu_f(tv.x)*w.x + silu_f(tv.y)*w.y + silu_f(tv.z)*w.z + silu_f(tv.w)*w.w;
    __shared__ float sred[4];
    #pragma unroll
    for (int off = 16; off; off >>= 1) p += __shfl_down_sync(0xffffffffu, p, off);
    if ((tid & 31) == 0) sred[tid >> 5] = p;
    __syncthreads();
    if (tid == 0) g_eblk[b] = sred[0]+sred[1]+sred[2]+sred[3];
}

__global__ __launch_bounds__(256) void k_energy(float* __restrict__ out)
{
    int g = blockIdx.x;
    int tid = threadIdx.x;
    float p = 0.f;
    #pragma unroll
    for (int k = 0; k < 4; k++) p += g_eblk[g*NBG + k*256 + tid];
    __shared__ float sred[8];
    #pragma unroll
    for (int off = 16; off; off >>= 1) p += __shfl_down_sync(0xffffffffu, p, off);
    if ((tid & 31) == 0) sred[tid >> 5] = p;
    __syncthreads();
    if (tid == 0) {
        float s = 0.f;
        #pragma unroll
        for (int w = 0; w < 8; w++) s += sred[w];
        out[OFF_E + g] = s;
        if (g == 0) out[OFF_LOSS] = 0.f;     // zero loss accumulator (runs before k_noise_loss)
    }
}

// ---------------- 9. graph_repr ----------------
__global__ __launch_bounds__(512) void k_graph(float* __restrict__ out)
{
    int g = blockIdx.x;
    int tid = threadIdx.x;       // channel
    float acc = 0.f;
    const float* hp = g_h + (size_t)g*NBG*HID + tid;
    for (int b = 0; b < NBG; b++) acc += hp[(size_t)b*HID];
    out[OFF_GR + g*HID + tid] = acc;
}

// ---------------- 10. pred_noise + loss ----------------
__global__ __launch_bounds__(256) void k_noise_loss(const float* __restrict__ noise,
                                                    float* __restrict__ out)
{
    int u = blockIdx.x*blockDim.x + threadIdx.x;
    float local = 0.f;
    if (u < NU) {
        int b = u >> 2;
        float dx = g_ZbB[b*3+0] - g_Zb0[b*3+0];
        float dy = g_ZbB[b*3+1] - g_Zb0[b*3+1];
        float dz = g_ZbB[b*3+2] - g_Zb0[b*3+2];
        out[OFF_PN + u*3+0] = dx;
        out[OFF_PN + u*3+1] = dy;
        out[OFF_PN + u*3+2] = dz;
        float ex = dx - noise[u*3+0];
        float ey = dy - noise[u*3+1];
        float ez = dz - noise[u*3+2];
        local = ex*ex + ey*ey + ez*ez;
    }
    __shared__ float sred[8];
    float p = local;
    #pragma unroll
    for (int off = 16; off; off >>= 1) p += __shfl_down_sync(0xffffffffu, p, off);
    if ((threadIdx.x & 31) == 0) sred[threadIdx.x >> 5] = p;
    __syncthreads();
    if (threadIdx.x == 0) {
        float s = 0.f;
        #pragma unroll
        for (int w = 0; w < 8; w++) s += sred[w];
        atomicAdd(out + OFF_LOSS, s * 0.0625f);   // 0.5/G
    }
}

// ---------------- 11. unit_repr & block_repr ----------------
__global__ void k_unit(float* __restrict__ out)
{
    int idx = blockIdx.x*blockDim.x + threadIdx.x;    // NU*128 float4
    if (idx >= NU*(HID/4)) return;
    int u = idx >> 7;
    int c = idx & 127;
    float4 h0 = ((const float4*)g_H0)[idx];
    float4 hb = ((const float4*)g_h)[(size_t)(u>>2)*128 + c];
    float4 r; r.x=h0.x+hb.x; r.y=h0.y+hb.y; r.z=h0.z+hb.z; r.w=h0.w+hb.w;
    ((float4*)(out + OFF_UR))[idx] = r;
}

__global__ void k_brepr(float* __restrict__ out)
{
    int idx = blockIdx.x*blockDim.x + threadIdx.x;    // NB*128 float4
    if (idx >= NB*(HID/4)) return;
    ((float4*)(out + OFF_BR))[idx] = ((const float4*)g_h)[idx];
}

// ---------------- launch ----------------
extern "C" void kernel_launch(void* const* d_in, const int* in_sizes, int n_in,
                              void* d_out, int out_size)
{
    const float* Z         = (const float*)d_in[0];
    const int*   B         = (const int*)  d_in[1];
    const int*   A         = (const int*)  d_in[2];
    const int*   AP        = (const int*)  d_in[3];
    const int*   seg       = (const int*)  d_in[6];
    const float* noise     = (const float*)d_in[7];
    const int*   nl        = (const int*)  d_in[8];
    const float* sigmas    = (const float*)d_in[9];
    const float* atom_emb  = (const float*)d_in[10];
    const float* pos_emb   = (const float*)d_in[11];
    const float* block_emb = (const float*)d_in[12];
    const float* edge_emb  = (const float*)d_in[13];
    const float* Wm        = (const float*)d_in[14];
    const float* We        = (const float*)d_in[15];
    const float* Wu        = (const float*)d_in[16];
    const float* wz        = (const float*)d_in[17];
    const float* W1        = (const float*)d_in[18];
    const float* b1        = (const float*)d_in[19];
    const float* W2        = (const float*)d_in[20];
    float* out = (float*)d_out;

    float *p_h, *p_hW, *p_agg, *p_t, *p_ZbA, *p_ZbB, *p_eW;
    cudaGetSymbolAddress((void**)&p_h,   g_h);
    cudaGetSymbolAddress((void**)&p_hW,  g_hW);
    cudaGetSymbolAddress((void**)&p_agg, g_agg);
    cudaGetSymbolAddress((void**)&p_t,   g_t);
    cudaGetSymbolAddress((void**)&p_ZbA, g_ZbA);
    cudaGetSymbolAddress((void**)&p_ZbB, g_ZbB);
    cudaGetSymbolAddress((void**)&p_eW,  g_eW);

    k_perturb<<<(NU+255)/256, 256>>>(Z, noise, nl, sigmas);
    k_zb0<<<(NB+255)/256, 256>>>();
    k_H0h<<<NB, 128>>>(A, AP, B, atom_emb, pos_emb, block_emb);
    k_ew<<<(LAY*2*HID+255)/256, 256>>>(edge_emb, We);

    k_knn_part<<<dim3(JP, 4, G), 256>>>(seg);
    k_knn_merge<<<(NB+255)/256, 256>>>();

    float* zold = p_ZbA;
    float* znew = p_ZbB;
    for (int l = 0; l < LAY; l++) {
        sgemm_tc<0,0><<<dim3(4,64), 256>>>(p_h, Wm + (size_t)l*HID*HID, p_hW, nullptr, nullptr);
        k_edge<<<NB, 128>>>(wz + l*HID, p_eW + l*2*HID, zold, znew);
        sgemm_tc<0,1><<<dim3(4,64), 256>>>(p_agg, Wu + (size_t)l*HID*HID, p_h, p_h, nullptr);
        float* tmp = zold; zold = znew; znew = tmp;
    }
    // after 3 swaps the final Zb lives in g_ZbB (A->B, B->A, A->B)

    sgemm_tc<1,2><<<dim3(4,64), 256>>>(p_h, W1, p_t, nullptr, b1);
    k_eblk<<<NB, 128>>>(W2);
    k_energy<<<G, 256>>>(out);
    k_graph<<<G, 512>>>(out);
    k_noise_loss<<<(NU+255)/256, 256>>>(noise, out);
    k_unit<<<(NU*(HID/4)+255)/256, 256>>>(out);
    k_brepr<<<(NB*(HID/4)+255)/256, 256>>>(out);
}

// round 12
// speedup vs baseline: 2.8199x; 1.0122x over previous
#include <cuda_runtime.h>
#include <math.h>
#include <stdint.h>

#define G    8
#define NBG  1024
#define APB  4
#define HID  512
#define ES   64
#define KNN  9
#define LAY  3
#define NB   (G*NBG)        // 8192
#define NU   (NB*APB)       // 32768
#define NE   (2*KNN)        // 18 edges per dst block
#define JP   4              // knn j-partitions

// output layout (float32, concatenated reference outputs)
#define OFF_E    0
#define OFF_PN   8
#define OFF_UR   98312            // 8 + 32768*3
#define OFF_BR   16875528         // + 32768*512
#define OFF_GR   21069832         // + 8192*512
#define OFF_LOSS 21073928         // + 8*512

// ---------------- scratch (static device globals; no allocations) ----------
__device__ float4 g_ZpS[NU];          // x,y,z,sq
__device__ float  g_H0[NU*HID];       // 64 MB
__device__ float  g_h[NB*HID];
__device__ float  g_hW[NB*HID];
__device__ float  g_agg[NB*HID];
__device__ float  g_Zb0[NB*3];
__device__ float  g_ZbA[NB*3];
__device__ float  g_ZbB[NB*3];
__device__ int    g_nbr[NB*NE];
__device__ float  g_eW[LAY*2*HID];
__device__ float  g_eblk[NB];
__device__ float  g_gpart[G*8*HID];
__device__ float  g_pD[NB*JP*2*KNN];  // partial knn distances
__device__ int    g_pI[NB*JP*2*KNN];  // partial knn indices (graph-local)

__device__ __forceinline__ float silu_f(float x){ return x / (1.0f + expf(-x)); }

__device__ __forceinline__ uint32_t f2tf32(float f){
    uint32_t u;
    asm("cvt.rna.tf32.f32 %0, %1;" : "=r"(u) : "f"(f));
    return u;
}

__device__ __forceinline__ void mma_tf32(float* d, const uint32_t* a, const uint32_t* b){
    asm volatile("mma.sync.aligned.m16n8k8.row.col.f32.tf32.tf32.f32 "
        "{%0,%1,%2,%3}, {%4,%5,%6,%7}, {%8,%9}, {%0,%1,%2,%3};"
        : "+f"(d[0]), "+f"(d[1]), "+f"(d[2]), "+f"(d[3])
        : "r"(a[0]), "r"(a[1]), "r"(a[2]), "r"(a[3]), "r"(b[0]), "r"(b[1]));
}

// ---------------- 1. perturb + sq + block means + eblk zero ----------------
__global__ void k_perturb(const float* __restrict__ Z, const float* __restrict__ noise,
                          const int* __restrict__ nl, const float* __restrict__ sigmas)
{
    int b = blockIdx.x*blockDim.x + threadIdx.x;
    if (b >= NB) return;
    int g = b >> 10;
    float s = sigmas[nl[g]];
    float mx=0.f, my=0.f, mz=0.f;
    #pragma unroll
    for (int a = 0; a < 4; a++) {
        int u = b*4 + a;
        float x = Z[u*3+0] + noise[u*3+0]*s;
        float y = Z[u*3+1] + noise[u*3+1]*s;
        float z = Z[u*3+2] + noise[u*3+2]*s;
        float4 v; v.x=x; v.y=y; v.z=z; v.w = x*x + y*y + z*z;
        g_ZpS[u] = v;
        mx += x; my += y; mz += z;
    }
    mx *= 0.25f; my *= 0.25f; mz *= 0.25f;
    g_Zb0[b*3+0]=mx; g_Zb0[b*3+1]=my; g_Zb0[b*3+2]=mz;
    g_ZbA[b*3+0]=mx; g_ZbA[b*3+1]=my; g_ZbA[b*3+2]=mz;
    g_eblk[b] = 0.f;
}

// ---------------- 2. fused H0 + block mean h ----------------
__global__ __launch_bounds__(128) void k_H0h(const int* __restrict__ A, const int* __restrict__ P,
                     const int* __restrict__ B,
                     const float* __restrict__ ae, const float* __restrict__ pe,
                     const float* __restrict__ be)
{
    int b = blockIdx.x;           // block index
    int c = threadIdx.x;          // float4 channel 0..127
    const float4* ae4 = (const float4*)ae;
    const float4* pe4 = (const float4*)pe;
    const float4* be4 = (const float4*)be;
    float4 bb = be4[B[b]*128 + c];
    float sx=0.f, sy=0.f, sz=0.f, sw=0.f;
    #pragma unroll
    for (int a = 0; a < 4; a++) {
        int u = b*4 + a;
        float4 av = ae4[A[u]*128 + c];
        float4 pv = pe4[P[u]*128 + c];
        float4 r;
        r.x = av.x + pv.x + bb.x;
        r.y = av.y + pv.y + bb.y;
        r.z = av.z + pv.z + bb.z;
        r.w = av.w + pv.w + bb.w;
        ((float4*)g_H0)[(size_t)u*128 + c] = r;
        sx += r.x; sy += r.y; sz += r.z; sw += r.w;
    }
    float4 hm; hm.x = sx*0.25f; hm.y = sy*0.25f; hm.z = sz*0.25f; hm.w = sw*0.25f;
    ((float4*)g_h)[(size_t)b*128 + c] = hm;
}

// ---------------- 3. eW[l][type][c] = edge_emb[type] @ We[l] ----------------
__global__ void k_ew(const float* __restrict__ ee, const float* __restrict__ We)
{
    int idx = blockIdx.x*blockDim.x + threadIdx.x;
    if (idx >= LAY*2*HID) return;
    int l = idx / (2*HID);
    int r = idx % (2*HID);
    int t = r / HID;
    int c = r % HID;
    float acc = 0.f;
    #pragma unroll 8
    for (int k = 0; k < ES; k++)
        acc += ee[t*ES+k] * We[(l*ES+k)*HID + c];
    g_eW[idx] = acc;
}

// ---------------- 4. KNN: partial top-9 over a j-quarter ----------------
__device__ __forceinline__ void ins9(float D, int j, float* bd, int* bi)
{
    if (D >= bd[8]) return;
    int p = 8;
    while (p > 0 && bd[p-1] > D) { bd[p]=bd[p-1]; bi[p]=bi[p-1]; --p; }
    bd[p]=D; bi[p]=j;
}

__device__ __forceinline__ void ins9lex(float D, int i, float* bd, int* bi)
{
    if (D > bd[8] || (D == bd[8] && i >= bi[8])) return;
    int p = 8;
    while (p > 0 && (bd[p-1] > D || (bd[p-1] == D && bi[p-1] > i))) {
        bd[p]=bd[p-1]; bi[p]=bi[p-1]; --p;
    }
    bd[p]=D; bi[p]=i;
}

__global__ __launch_bounds__(256) void k_knn_part(const int* __restrict__ seg)
{
    __shared__ float4 sa[256*APB];          // atoms of this j-quarter
    __shared__ int sseg[256];
    int part  = blockIdx.x;                 // 0..3
    int chunk = blockIdx.y;                 // 0..3 (dst chunk of 256)
    int g     = blockIdx.z;                 // graph
    int jbase = part*256;                   // local block base of this quarter
    int abase = g*NBG*APB + jbase*APB;
    for (int i = threadIdx.x; i < 256*APB; i += 256) sa[i] = g_ZpS[abase + i];
    sseg[threadIdx.x] = seg[g*NBG + jbase + threadIdx.x];
    __syncthreads();

    int ib = chunk*256 + threadIdx.x;       // local dst block
    int gd = g*NBG + ib;                    // global dst block
    float4 o0 = g_ZpS[gd*4+0], o1 = g_ZpS[gd*4+1], o2 = g_ZpS[gd*4+2], o3 = g_ZpS[gd*4+3];
    int myseg = seg[gd];

    float bd0[KNN], bd1[KNN]; int bi0[KNN], bi1[KNN];
    #pragma unroll
    for (int k = 0; k < KNN; k++) { bd0[k]=3.0e38f; bd1[k]=3.0e38f; bi0[k]=0x3fffffff; bi1[k]=0x3fffffff; }

    for (int jj = 0; jj < 256; jj++) {
        float4 c0 = sa[jj*4+0], c1 = sa[jj*4+1], c2 = sa[jj*4+2], c3 = sa[jj*4+3];
        #define DD(o,c) ((o).w + (c).w - 2.0f*((o).x*(c).x + (o).y*(c).y + (o).z*(c).z))
        float d = DD(o0,c0);
        d = fminf(d, DD(o0,c1)); d = fminf(d, DD(o0,c2)); d = fminf(d, DD(o0,c3));
        d = fminf(d, DD(o1,c0)); d = fminf(d, DD(o1,c1)); d = fminf(d, DD(o1,c2)); d = fminf(d, DD(o1,c3));
        d = fminf(d, DD(o2,c0)); d = fminf(d, DD(o2,c1)); d = fminf(d, DD(o2,c2)); d = fminf(d, DD(o2,c3));
        d = fminf(d, DD(o3,c0)); d = fminf(d, DD(o3,c1)); d = fminf(d, DD(o3,c2)); d = fminf(d, DD(o3,c3));
        #undef DD
        int j = jbase + jj;
        if (sseg[jj] == myseg) {
            if (j != ib) ins9(d, j, bd0, bi0);
        } else {
            ins9(d, j, bd1, bi1);
        }
    }
    size_t base = ((size_t)gd*JP + part)*2*KNN;
    #pragma unroll
    for (int k = 0; k < KNN; k++) {
        g_pD[base + k] = bd0[k];          g_pI[base + k] = bi0[k];
        g_pD[base + KNN + k] = bd1[k];    g_pI[base + KNN + k] = bi1[k];
    }
}

__global__ void k_knn_merge()
{
    int b = blockIdx.x*blockDim.x + threadIdx.x;
    if (b >= NB) return;
    int goff = (b >> 10) * NBG;            // graph offset
    #pragma unroll
    for (int list = 0; list < 2; list++) {
        float od[KNN]; int oi[KNN];
        #pragma unroll
        for (int k = 0; k < KNN; k++) { od[k]=3.1e38f; oi[k]=0x7fffffff; }
        for (int part = 0; part < JP; part++) {
            size_t base = ((size_t)b*JP + part)*2*KNN + list*KNN;
            #pragma unroll
            for (int k = 0; k < KNN; k++)
                ins9lex(g_pD[base+k], g_pI[base+k], od, oi);
        }
        #pragma unroll
        for (int k = 0; k < KNN; k++)
            g_nbr[b*NE + list*KNN + k] = goff + oi[k];
    }
}

// ---------------- 5. TF32 tensor-core GEMM -------------------------------
// C[8192,512] = op(A)[8192,512] @ B[512,512]
// EPI 0: C = acc;  EPI 1: C = addC + silu(acc);
// EPI 2: energy head — no C store; atomicAdd silu(acc+bias)·W2 into g_eblk.
// SILU_A: apply silu to A elements during staging.
// 128x128 CTA tile, 8 warps (2x4), warp tile 64x32, BK=16, double buffered.
template<int SILU_A, int EPI>
__global__ __launch_bounds__(256) void sgemm_tc(
    const float* __restrict__ A, const float* __restrict__ Bm,
    float* __restrict__ C, const float* __restrict__ addC,
    const float* __restrict__ bias, const float* __restrict__ W2p)
{
    __shared__ uint32_t As[2][2][8][32][4];   // [buf][k8][mtile][lane][slot]
    __shared__ uint32_t Bs[2][2][16][32][2];  // [buf][k8][ntile][lane][slot]
    const int tid  = threadIdx.x;
    const int lane = tid & 31, wid = tid >> 5;
    const int wm = wid >> 2, wn = wid & 3;        // warp grid 2(M) x 4(N)
    const int brow = blockIdx.y*128, bcol = blockIdx.x*128;
    const int gg = lane >> 2, tt = lane & 3;
    const int qa = tid*2;

    float acc[4][4][4];
    #pragma unroll
    for (int mt=0;mt<4;mt++){
        #pragma unroll
        for (int nt=0;nt<4;nt++){
            #pragma unroll
            for (int r=0;r<4;r++) acc[mt][nt][r]=0.f;
        }
    }

    auto loadA = [&](int q, int kp)->float4 {
        int r = q >> 2, cq = q & 3;
        return *(const float4*)(A + (size_t)(brow+r)*HID + kp + 4*cq);
    };
    auto loadB = [&](int q, int kp)->float4 {
        int kb = q >> 5, cq = q & 31;
        return *(const float4*)(Bm + (size_t)(kp+kb)*HID + bcol + 4*cq);
    };
    auto stageA = [&](int buf, float4 v, int q){
        int r = q >> 2, cq = q & 3;
        int mt = r >> 4, rr = r & 15, g2 = rr & 7, rh = rr >> 3;
        float vv[4] = {v.x, v.y, v.z, v.w};
        #pragma unroll
        for (int j=0;j<4;j++){
            int kc = 4*cq + j, ks = kc >> 3, ck = kc & 7, tl = ck & 3, ch = ck >> 2;
            float f = SILU_A ? silu_f(vv[j]) : vv[j];
            As[buf][ks][mt][g2*4+tl][rh + 2*ch] = f2tf32(f);
        }
    };
    auto stageB = [&](int buf, float4 v, int q){
        int kb = q >> 5, cq = q & 31;
        int ks = kb >> 3, kk = kb & 7, tl = kk & 3, s = kk >> 2;
        float vv[4] = {v.x, v.y, v.z, v.w};
        #pragma unroll
        for (int j=0;j<4;j++){
            int nl = 4*cq + j, nt = nl >> 3, nn = nl & 7;
            Bs[buf][ks][nt][nn*4+tl][s] = f2tf32(vv[j]);
        }
    };

    // prologue: panel 0
    stageA(0, loadA(qa,0), qa);   stageA(0, loadA(qa+1,0), qa+1);
    stageB(0, loadB(qa,0), qa);   stageB(0, loadB(qa+1,0), qa+1);
    __syncthreads();

    float4 pa0, pa1, pb0, pb1;
    for (int p = 0; p < 32; p++) {
        int buf = p & 1;
        if (p < 31) {
            int kp = (p+1)*16;
            pa0 = loadA(qa,kp);   pa1 = loadA(qa+1,kp);
            pb0 = loadB(qa,kp);   pb1 = loadB(qa+1,kp);
        }
        #pragma unroll
        for (int ks = 0; ks < 2; ks++) {
            uint32_t af[4][4], bf[4][2];
            #pragma unroll
            for (int mt=0;mt<4;mt++)
                *(uint4*)af[mt] = *(const uint4*)&As[buf][ks][wm*4+mt][lane][0];
            #pragma unroll
            for (int nt=0;nt<4;nt++)
                *(uint2*)bf[nt] = *(const uint2*)&Bs[buf][ks][wn*4+nt][lane][0];
            #pragma unroll
            for (int mt=0;mt<4;mt++){
                #pragma unroll
                for (int nt=0;nt<4;nt++)
                    mma_tf32(acc[mt][nt], af[mt], bf[nt]);
            }
        }
        if (p < 31) {
            int nb = buf ^ 1;
            stageA(nb, pa0, qa);   stageA(nb, pa1, qa+1);
            stageB(nb, pb0, qa);   stageB(nb, pb1, qa+1);
        }
        __syncthreads();
    }

    // epilogue
    #pragma unroll
    for (int mt=0;mt<4;mt++){
        int row0 = brow + wm*64 + mt*16 + gg;
        int row1 = row0 + 8;
        float es0 = 0.f, es1 = 0.f;     // EPI2 per-row energy partials
        #pragma unroll
        for (int nt=0;nt<4;nt++){
            int col = bcol + wn*32 + nt*8 + 2*tt;
            float v0 = acc[mt][nt][0], v1 = acc[mt][nt][1];
            float v2 = acc[mt][nt][2], v3 = acc[mt][nt][3];
            if (EPI == 1) {
                float2 c0 = *(const float2*)(addC + (size_t)row0*HID + col);
                float2 c1 = *(const float2*)(addC + (size_t)row1*HID + col);
                v0 = c0.x + silu_f(v0); v1 = c0.y + silu_f(v1);
                v2 = c1.x + silu_f(v2); v3 = c1.y + silu_f(v3);
            }
            if (EPI == 2) {
                float2 bb = *(const float2*)(bias + col);
                float2 w2 = *(const float2*)(W2p + col);
                v0 += bb.x; v1 += bb.y; v2 += bb.x; v3 += bb.y;
                es0 += silu_f(v0)*w2.x + silu_f(v1)*w2.y;
                es1 += silu_f(v2)*w2.x + silu_f(v3)*w2.y;
            } else {
                float2 o0; o0.x=v0; o0.y=v1;
                float2 o1; o1.x=v2; o1.y=v3;
                *(float2*)(C + (size_t)row0*HID + col) = o0;
                *(float2*)(C + (size_t)row1*HID + col) = o1;
            }
        }
        if (EPI == 2) {
            atomicAdd(&g_eblk[row0], es0);
            atomicAdd(&g_eblk[row1], es1);
        }
    }
}

// ---------------- 6. fused edge/message kernel ----------------
__global__ __launch_bounds__(128) void k_edge(
    const float* __restrict__ wz_l, const float* __restrict__ eWl,
    const float* __restrict__ Zb_old, float* __restrict__ Zb_new)
{
    int d = blockIdx.x;
    int tid = threadIdx.x;                      // 128 threads, 4 channels each
    const float4* hW4 = (const float4*)g_hW;
    float4 hd  = hW4[(size_t)d*128 + tid];
    float4 wzv = ((const float4*)wz_l)[tid];
    float4 ew0 = ((const float4*)eWl)[tid];
    float4 ew1 = ((const float4*)(eWl + HID))[tid];
    float4 ag = make_float4(0.f,0.f,0.f,0.f);

    __shared__ int   snbr[NE];
    __shared__ float sp[NE][4];
    __shared__ float sx[NE], sy[NE], sz[NE];
    if (tid < NE) snbr[tid] = g_nbr[d*NE + tid];
    __syncthreads();

    int wid = tid >> 5, lane = tid & 31;
    #pragma unroll
    for (int e = 0; e < NE; e++) {
        int s = snbr[e];
        float4 ew = (e < KNN) ? ew0 : ew1;
        float4 hs = hW4[(size_t)s*128 + tid];
        float m0 = silu_f(hs.x + hd.x + ew.x);
        float m1 = silu_f(hs.y + hd.y + ew.y);
        float m2 = silu_f(hs.z + hd.z + ew.z);
        float m3 = silu_f(hs.w + hd.w + ew.w);
        ag.x += m0; ag.y += m1; ag.z += m2; ag.w += m3;
        float p = m0*wzv.x + m1*wzv.y + m2*wzv.z + m3*wzv.w;
        #pragma unroll
        for (int off = 16; off; off >>= 1) p += __shfl_down_sync(0xffffffffu, p, off);
        if (lane == 0) sp[e][wid] = p;
    }
    __syncthreads();

    float Zdx = Zb_old[d*3+0], Zdy = Zb_old[d*3+1], Zdz = Zb_old[d*3+2];
    if (tid < NE) {
        float coef = tanhf(sp[tid][0] + sp[tid][1] + sp[tid][2] + sp[tid][3]);
        int s = snbr[tid];
        sx[tid] = (Zb_old[s*3+0] - Zdx)*coef;
        sy[tid] = (Zb_old[s*3+1] - Zdy)*coef;
        sz[tid] = (Zb_old[s*3+2] - Zdz)*coef;
    }
    __syncthreads();

    ((float4*)g_agg)[(size_t)d*128 + tid] = ag;
    if (tid == 0) {
        float zx=0.f, zy=0.f, zz=0.f;
        #pragma unroll
        for (int e = 0; e < NE; e++) { zx += sx[e]; zy += sy[e]; zz += sz[e]; }
        const float inv = 1.0f / (2*KNN);
        Zb_new[d*3+0] = Zdx + zx*inv;
        Zb_new[d*3+1] = Zdy + zy*inv;
        Zb_new[d*3+2] = Zdz + zz*inv;
    }
}

// ---------------- 7. energy reduce ----------------
__global__ __launch_bounds__(256) void k_energy(float* __restrict__ out)
{
    int g = blockIdx.x;
    int tid = threadIdx.x;
    float p = 0.f;
    #pragma unroll
    for (int k = 0; k < 4; k++) p += g_eblk[g*NBG + k*256 + tid];
    __shared__ float sred[8];
    #pragma unroll
    for (int off = 16; off; off >>= 1) p += __shfl_down_sync(0xffffffffu, p, off);
    if ((tid & 31) == 0) sred[tid >> 5] = p;
    __syncthreads();
    if (tid == 0) {
        float s = 0.f;
        #pragma unroll
        for (int w = 0; w < 8; w++) s += sred[w];
        out[OFF_E + g] = s;
        if (g == 0) out[OFF_LOSS] = 0.f;     // zero loss accumulator (runs before k_noise_loss)
    }
}

// ---------------- 8. graph_repr (two-phase) ----------------
__global__ __launch_bounds__(512) void k_graphp()
{
    int g = blockIdx.y;
    int chunk = blockIdx.x;      // 0..7, 128 blocks each
    int tid = threadIdx.x;       // channel
    float acc = 0.f;
    const float* hp = g_h + (size_t)(g*NBG + chunk*128)*HID + tid;
    for (int b = 0; b < 128; b++) acc += hp[(size_t)b*HID];
    g_gpart[(g*8 + chunk)*HID + tid] = acc;
}

__global__ __launch_bounds__(512) void k_graph2(float* __restrict__ out)
{
    int g = blockIdx.x;
    int tid = threadIdx.x;
    float acc = 0.f;
    #pragma unroll
    for (int c = 0; c < 8; c++) acc += g_gpart[(g*8 + c)*HID + tid];
    out[OFF_GR + g*HID + tid] = acc;
}

// ---------------- 9. pred_noise + loss ----------------
__global__ __launch_bounds__(256) void k_noise_loss(const float* __restrict__ noise,
                                                    float* __restrict__ out)
{
    int u = blockIdx.x*blockDim.x + threadIdx.x;
    float local = 0.f;
    if (u < NU) {
        int b = u >> 2;
        float dx = g_ZbB[b*3+0] - g_Zb0[b*3+0];
        float dy = g_ZbB[b*3+1] - g_Zb0[b*3+1];
        float dz = g_ZbB[b*3+2] - g_Zb0[b*3+2];
        out[OFF_PN + u*3+0] = dx;
        out[OFF_PN + u*3+1] = dy;
        out[OFF_PN + u*3+2] = dz;
        float ex = dx - noise[u*3+0];
        float ey = dy - noise[u*3+1];
        float ez = dz - noise[u*3+2];
        local = ex*ex + ey*ey + ez*ez;
    }
    __shared__ float sred[8];
    float p = local;
    #pragma unroll
    for (int off = 16; off; off >>= 1) p += __shfl_down_sync(0xffffffffu, p, off);
    if ((threadIdx.x & 31) == 0) sred[threadIdx.x >> 5] = p;
    __syncthreads();
    if (threadIdx.x == 0) {
        float s = 0.f;
        #pragma unroll
        for (int w = 0; w < 8; w++) s += sred[w];
        atomicAdd(out + OFF_LOSS, s * 0.0625f);   // 0.5/G
    }
}

// ---------------- 10. unit_repr & block_repr ----------------
__global__ void k_unit(float* __restrict__ out)
{
    int idx = blockIdx.x*blockDim.x + threadIdx.x;    // NU*128 float4
    if (idx >= NU*(HID/4)) return;
    int u = idx >> 7;
    int c = idx & 127;
    float4 h0 = ((const float4*)g_H0)[idx];
    float4 hb = ((const float4*)g_h)[(size_t)(u>>2)*128 + c];
    float4 r; r.x=h0.x+hb.x; r.y=h0.y+hb.y; r.z=h0.z+hb.z; r.w=h0.w+hb.w;
    ((float4*)(out + OFF_UR))[idx] = r;
}

__global__ void k_brepr(float* __restrict__ out)
{
    int idx = blockIdx.x*blockDim.x + threadIdx.x;    // NB*128 float4
    if (idx >= NB*(HID/4)) return;
    ((float4*)(out + OFF_BR))[idx] = ((const float4*)g_h)[idx];
}

// ---------------- launch ----------------
extern "C" void kernel_launch(void* const* d_in, const int* in_sizes, int n_in,
                              void* d_out, int out_size)
{
    const float* Z         = (const float*)d_in[0];
    const int*   B         = (const int*)  d_in[1];
    const int*   A         = (const int*)  d_in[2];
    const int*   AP        = (const int*)  d_in[3];
    const int*   seg       = (const int*)  d_in[6];
    const float* noise     = (const float*)d_in[7];
    const int*   nl        = (const int*)  d_in[8];
    const float* sigmas    = (const float*)d_in[9];
    const float* atom_emb  = (const float*)d_in[10];
    const float* pos_emb   = (const float*)d_in[11];
    const float* block_emb = (const float*)d_in[12];
    const float* edge_emb  = (const float*)d_in[13];
    const float* Wm        = (const float*)d_in[14];
    const float* We        = (const float*)d_in[15];
    const float* Wu        = (const float*)d_in[16];
    const float* wz        = (const float*)d_in[17];
    const float* W1        = (const float*)d_in[18];
    const float* b1        = (const float*)d_in[19];
    const float* W2        = (const float*)d_in[20];
    float* out = (float*)d_out;

    float *p_h, *p_hW, *p_agg, *p_ZbA, *p_ZbB, *p_eW;
    cudaGetSymbolAddress((void**)&p_h,   g_h);
    cudaGetSymbolAddress((void**)&p_hW,  g_hW);
    cudaGetSymbolAddress((void**)&p_agg, g_agg);
    cudaGetSymbolAddress((void**)&p_ZbA, g_ZbA);
    cudaGetSymbolAddress((void**)&p_ZbB, g_ZbB);
    cudaGetSymbolAddress((void**)&p_eW,  g_eW);

    k_perturb<<<(NB+255)/256, 256>>>(Z, noise, nl, sigmas);
    k_H0h<<<NB, 128>>>(A, AP, B, atom_emb, pos_emb, block_emb);
    k_ew<<<(LAY*2*HID+255)/256, 256>>>(edge_emb, We);

    k_knn_part<<<dim3(JP, 4, G), 256>>>(seg);
    k_knn_merge<<<(NB+255)/256, 256>>>();

    float* zold = p_ZbA;
    float* znew = p_ZbB;
    for (int l = 0; l < LAY; l++) {
        sgemm_tc<0,0><<<dim3(4,64), 256>>>(p_h, Wm + (size_t)l*HID*HID, p_hW, nullptr, nullptr, nullptr);
        k_edge<<<NB, 128>>>(wz + l*HID, p_eW + l*2*HID, zold, znew);
        sgemm_tc<0,1><<<dim3(4,64), 256>>>(p_agg, Wu + (size_t)l*HID*HID, p_h, p_h, nullptr, nullptr);
        float* tmp = zold; zold = znew; znew = tmp;
    }
    // after 3 swaps the final Zb lives in g_ZbB (A->B, B->A, A->B)

    sgemm_tc<1,2><<<dim3(4,64), 256>>>(p_h, W1, nullptr, nullptr, b1, W2);
    k_energy<<<G, 256>>>(out);
    k_graphp<<<dim3(8, G), 512>>>();
    k_graph2<<<G, 512>>>(out);
    k_noise_loss<<<(NU+255)/256, 256>>>(noise, out);
    k_unit<<<(NU*(HID/4)+255)/256, 256>>>(out);
    k_brepr<<<(NB*(HID/4)+255)/256, 256>>>(out);
}

// round 14
// speedup vs baseline: 3.3825x; 1.1995x over previous
#include <cuda_runtime.h>
#include <cuda_fp16.h>
#include <math.h>
#include <stdint.h>

#define G    8
#define NBG  1024
#define APB  4
#define HID  512
#define ES   64
#define KNN  9
#define LAY  3
#define NB   (G*NBG)        // 8192
#define NU   (NB*APB)       // 32768
#define NE   (2*KNN)        // 18 edges per dst block
#define JP   8              // knn j-partitions

// output layout (float32, concatenated reference outputs)
#define OFF_E    0
#define OFF_PN   8
#define OFF_UR   98312            // 8 + 32768*3
#define OFF_BR   16875528         // + 32768*512
#define OFF_GR   21069832         // + 8192*512
#define OFF_LOSS 21073928         // + 8*512

// ---------------- scratch (static device globals; no allocations) ----------
__device__ float4 g_ZpS[NU];
__device__ float  g_H0[NU*HID];
__device__ float  g_h[NB*HID];
__device__ float  g_hW[NB*HID];
__device__ float  g_agg[NB*HID];
__device__ float  g_Zb0[NB*3];
__device__ float  g_ZbA[NB*3];
__device__ float  g_ZbB[NB*3];
__device__ int    g_nbr[NB*NE];
__device__ float  g_eW[LAY*2*HID];
__device__ float  g_eblk[NB];
__device__ float  g_gpart[G*8*HID];
__device__ float  g_pD[NB*JP*2*KNN];
__device__ int    g_pI[NB*JP*2*KNN];
__device__ uint32_t g_Wh[7*32*64*32*2];   // 7 weights, fp16 fragment order

__device__ __forceinline__ float silu_f(float x){ return x / (1.0f + expf(-x)); }

__device__ __forceinline__ void mma16(float* d, const uint32_t* a, const uint32_t* b){
    asm volatile("mma.sync.aligned.m16n8k16.row.col.f32.f16.f16.f32 "
        "{%0,%1,%2,%3}, {%4,%5,%6,%7}, {%8,%9}, {%0,%1,%2,%3};"
        : "+f"(d[0]), "+f"(d[1]), "+f"(d[2]), "+f"(d[3])
        : "r"(a[0]), "r"(a[1]), "r"(a[2]), "r"(a[3]), "r"(b[0]), "r"(b[1]));
}

__device__ __forceinline__ uint32_t pack_h2(float lo, float hi){
    __half2 h = __floats2half2_rn(lo, hi);
    return *(uint32_t*)&h;
}

// ---------------- 1. perturb + sq + block means + eblk zero ----------------
__global__ void k_perturb(const float* __restrict__ Z, const float* __restrict__ noise,
                          const int* __restrict__ nl, const float* __restrict__ sigmas)
{
    int b = blockIdx.x*blockDim.x + threadIdx.x;
    if (b >= NB) return;
    int g = b >> 10;
    float s = sigmas[nl[g]];
    float mx=0.f, my=0.f, mz=0.f;
    #pragma unroll
    for (int a = 0; a < 4; a++) {
        int u = b*4 + a;
        float x = Z[u*3+0] + noise[u*3+0]*s;
        float y = Z[u*3+1] + noise[u*3+1]*s;
        float z = Z[u*3+2] + noise[u*3+2]*s;
        float4 v; v.x=x; v.y=y; v.z=z; v.w = x*x + y*y + z*z;
        g_ZpS[u] = v;
        mx += x; my += y; mz += z;
    }
    mx *= 0.25f; my *= 0.25f; mz *= 0.25f;
    g_Zb0[b*3+0]=mx; g_Zb0[b*3+1]=my; g_Zb0[b*3+2]=mz;
    g_ZbA[b*3+0]=mx; g_ZbA[b*3+1]=my; g_ZbA[b*3+2]=mz;
    g_eblk[b] = 0.f;
}

// ---------------- 2. fused H0 + block mean h ----------------
__global__ __launch_bounds__(128) void k_H0h(const int* __restrict__ A, const int* __restrict__ P,
                     const int* __restrict__ B,
                     const float* __restrict__ ae, const float* __restrict__ pe,
                     const float* __restrict__ be)
{
    int b = blockIdx.x;
    int c = threadIdx.x;
    const float4* ae4 = (const float4*)ae;
    const float4* pe4 = (const float4*)pe;
    const float4* be4 = (const float4*)be;
    float4 bb = be4[B[b]*128 + c];
    float sx=0.f, sy=0.f, sz=0.f, sw=0.f;
    #pragma unroll
    for (int a = 0; a < 4; a++) {
        int u = b*4 + a;
        float4 av = ae4[A[u]*128 + c];
        float4 pv = pe4[P[u]*128 + c];
        float4 r;
        r.x = av.x + pv.x + bb.x;
        r.y = av.y + pv.y + bb.y;
        r.z = av.z + pv.z + bb.z;
        r.w = av.w + pv.w + bb.w;
        ((float4*)g_H0)[(size_t)u*128 + c] = r;
        sx += r.x; sy += r.y; sz += r.z; sw += r.w;
    }
    float4 hm; hm.x = sx*0.25f; hm.y = sy*0.25f; hm.z = sz*0.25f; hm.w = sw*0.25f;
    ((float4*)g_h)[(size_t)b*128 + c] = hm;
}

// ---------------- 3. eW precompute ----------------
__global__ void k_ew(const float* __restrict__ ee, const float* __restrict__ We)
{
    int idx = blockIdx.x*blockDim.x + threadIdx.x;
    if (idx >= LAY*2*HID) return;
    int l = idx / (2*HID);
    int r = idx % (2*HID);
    int t = r / HID;
    int c = r % HID;
    float acc = 0.f;
    #pragma unroll 8
    for (int k = 0; k < ES; k++)
        acc += ee[t*ES+k] * We[(l*ES+k)*HID + c];
    g_eW[idx] = acc;
}

// ---------------- 4. weight prep: fp16 fragment-order layout ----------------
// g_Wh[w][kp(32)][ntg(64)][lane(32)][reg(2)] : b-fragments for m16n8k16.
// b0 (reg 0) = { W[kp*16+2t][n], W[kp*16+2t+1][n] },  t=lane&3, n=ntg*8+(lane>>2)
// b1 (reg 1) = same with k += 8.
__global__ __launch_bounds__(256) void k_wprep_h(const float* __restrict__ Wm,
                                                 const float* __restrict__ Wu,
                                                 const float* __restrict__ W1)
{
    int kp = blockIdx.x, w = blockIdx.y;
    const float* W = (w < 3) ? (Wm + (size_t)w*HID*HID)
                   : (w < 6) ? (Wu + (size_t)(w-3)*HID*HID)
                             : W1;
    uint32_t* dst = g_Wh + (((size_t)w*32 + kp)*64*32*2);
    for (int i = threadIdx.x; i < 64*32*2; i += 256) {
        int ntg  = i >> 6;
        int rem  = i & 63;
        int lane = rem >> 1;
        int reg  = rem & 1;
        int k = kp*16 + reg*8 + 2*(lane & 3);
        int n = ntg*8 + (lane >> 2);
        float lo = W[(size_t)k*HID + n];
        float hi = W[(size_t)(k+1)*HID + n];
        dst[i] = pack_h2(lo, hi);
    }
}

// ---------------- 5. KNN ----------------
__device__ __forceinline__ void ins9(float D, int j, float* bd, int* bi)
{
    if (D >= bd[8]) return;
    int p = 8;
    while (p > 0 && bd[p-1] > D) { bd[p]=bd[p-1]; bi[p]=bi[p-1]; --p; }
    bd[p]=D; bi[p]=j;
}

__device__ __forceinline__ void ins9lex(float D, int i, float* bd, int* bi)
{
    if (D > bd[8] || (D == bd[8] && i >= bi[8])) return;
    int p = 8;
    while (p > 0 && (bd[p-1] > D || (bd[p-1] == D && bi[p-1] > i))) {
        bd[p]=bd[p-1]; bi[p]=bi[p-1]; --p;
    }
    bd[p]=D; bi[p]=i;
}

#define JBL (NBG/JP)    // 128 blocks per j-partition

__global__ __launch_bounds__(256) void k_knn_part(const int* __restrict__ seg)
{
    __shared__ float4 sa[JBL*APB];          // 512 atoms
    __shared__ int sseg[JBL];
    int part  = blockIdx.x;                 // 0..7
    int chunk = blockIdx.y;                 // 0..3
    int g     = blockIdx.z;
    int jbase = part*JBL;
    int abase = g*NBG*APB + jbase*APB;
    for (int i = threadIdx.x; i < JBL*APB; i += 256) sa[i] = g_ZpS[abase + i];
    if (threadIdx.x < JBL) sseg[threadIdx.x] = seg[g*NBG + jbase + threadIdx.x];
    __syncthreads();

    int ib = chunk*256 + threadIdx.x;
    int gd = g*NBG + ib;
    float4 o0 = g_ZpS[gd*4+0], o1 = g_ZpS[gd*4+1], o2 = g_ZpS[gd*4+2], o3 = g_ZpS[gd*4+3];
    int myseg = seg[gd];

    float bd0[KNN], bd1[KNN]; int bi0[KNN], bi1[KNN];
    #pragma unroll
    for (int k = 0; k < KNN; k++) { bd0[k]=3.0e38f; bd1[k]=3.0e38f; bi0[k]=0x3fffffff; bi1[k]=0x3fffffff; }

    for (int jj = 0; jj < JBL; jj++) {
        float4 c0 = sa[jj*4+0], c1 = sa[jj*4+1], c2 = sa[jj*4+2], c3 = sa[jj*4+3];
        #define DD(o,c) ((o).w + (c).w - 2.0f*((o).x*(c).x + (o).y*(c).y + (o).z*(c).z))
        float d = DD(o0,c0);
        d = fminf(d, DD(o0,c1)); d = fminf(d, DD(o0,c2)); d = fminf(d, DD(o0,c3));
        d = fminf(d, DD(o1,c0)); d = fminf(d, DD(o1,c1)); d = fminf(d, DD(o1,c2)); d = fminf(d, DD(o1,c3));
        d = fminf(d, DD(o2,c0)); d = fminf(d, DD(o2,c1)); d = fminf(d, DD(o2,c2)); d = fminf(d, DD(o2,c3));
        d = fminf(d, DD(o3,c0)); d = fminf(d, DD(o3,c1)); d = fminf(d, DD(o3,c2)); d = fminf(d, DD(o3,c3));
        #undef DD
        int j = jbase + jj;
        if (sseg[jj] == myseg) {
            if (j != ib) ins9(d, j, bd0, bi0);
        } else {
            ins9(d, j, bd1, bi1);
        }
    }
    size_t base = ((size_t)gd*JP + part)*2*KNN;
    #pragma unroll
    for (int k = 0; k < KNN; k++) {
        g_pD[base + k] = bd0[k];          g_pI[base + k] = bi0[k];
        g_pD[base + KNN + k] = bd1[k];    g_pI[base + KNN + k] = bi1[k];
    }
}

__global__ void k_knn_merge()
{
    int b = blockIdx.x*blockDim.x + threadIdx.x;
    if (b >= NB) return;
    int goff = (b >> 10) * NBG;
    #pragma unroll
    for (int list = 0; list < 2; list++) {
        float od[KNN]; int oi[KNN];
        #pragma unroll
        for (int k = 0; k < KNN; k++) { od[k]=3.1e38f; oi[k]=0x7fffffff; }
        for (int part = 0; part < JP; part++) {
            size_t base = ((size_t)b*JP + part)*2*KNN + list*KNN;
            #pragma unroll
            for (int k = 0; k < KNN; k++)
                ins9lex(g_pD[base+k], g_pI[base+k], od, oi);
        }
        #pragma unroll
        for (int k = 0; k < KNN; k++)
            g_nbr[b*NE + list*KNN + k] = goff + oi[k];
    }
}

// ---------------- 6. fp16 tensor-core GEMM ---------------------------------
// C[8192,512] = op(A)[8192,512] @ W[512,512], W pre-staged fp16 frags in g_Wh.
// EPI 0: C = acc;  EPI 1: C = addC + silu(acc);
// EPI 2: energy head — atomicAdd_row( silu(acc+bias)·W2 ), no C store.
// 128x128 CTA tile, 8 warps (2x4), warp tile 64x32, BK=16 double buffered.
// A staged in smem in fragment order (LDS.128/frag); B direct gmem LDG.64.
template<int SILU_A, int EPI>
__global__ __launch_bounds__(256) void gemm_h(
    const float* __restrict__ A, const uint32_t* __restrict__ Bh,
    float* __restrict__ C, const float* __restrict__ addC,
    const float* __restrict__ bias, const float* __restrict__ W2p)
{
    __shared__ uint32_t As[2][8][32][4];     // [buf][mtile][lane][reg]
    const int tid  = threadIdx.x;
    const int lane = tid & 31, wid = tid >> 5;
    const int wm = wid >> 2, wn = wid & 3;
    const int brow = blockIdx.y*128;
    const int bcol = blockIdx.x*128;
    const int gg = lane >> 2, tt = lane & 3;
    const int qa = tid*2;

    float acc[4][4][4];
    #pragma unroll
    for (int mt=0;mt<4;mt++){
        #pragma unroll
        for (int nt=0;nt<4;nt++){
            #pragma unroll
            for (int r=0;r<4;r++) acc[mt][nt][r]=0.f;
        }
    }

    auto loadA = [&](int q, int kp)->float4 {
        int r = q >> 2, cq = q & 3;
        return *(const float4*)(A + (size_t)(brow+r)*HID + kp + 4*cq);
    };
    auto stageA = [&](int buf, float4 v, int q){
        int r = q >> 2, cq = q & 3;
        int mt = r >> 4, rr = r & 15, g2 = rr & 7, hi = rr >> 3;
        float vv[4] = {v.x, v.y, v.z, v.w};
        if (SILU_A) {
            #pragma unroll
            for (int j=0;j<4;j++) vv[j] = silu_f(vv[j]);
        }
        #pragma unroll
        for (int j=0;j<2;j++){
            int kc = 4*cq + 2*j;
            int lane_t = g2*4 + ((kc & 7) >> 1);
            int reg = hi + 2*(kc >> 3);
            As[buf][mt][lane_t][reg] = pack_h2(vv[2*j], vv[2*j+1]);
        }
    };
    // B fragment pointer for this warp/lane: ntg = bcol/8 + wn*4 + nt
    const uint32_t* bptr = Bh + (((size_t)(blockIdx.x*16 + wn*4))*32 + lane)*2;
    auto loadB = [&](int nt, int kp)->uint2 {
        return *(const uint2*)(bptr + ((size_t)kp*64 + nt)*64);
    };

    // prologue
    stageA(0, loadA(qa,0), qa);  stageA(0, loadA(qa+1,0), qa+1);
    uint32_t bf[4][2];
    #pragma unroll
    for (int nt=0;nt<4;nt++) *(uint2*)bf[nt] = loadB(nt, 0);
    __syncthreads();

    float4 pa0, pa1;
    uint32_t bfn[4][2];
    for (int p = 0; p < 32; p++) {
        int buf = p & 1;
        if (p < 31) {
            int kp = (p+1)*16;
            pa0 = loadA(qa,kp);  pa1 = loadA(qa+1,kp);
            #pragma unroll
            for (int nt=0;nt<4;nt++) *(uint2*)bfn[nt] = loadB(nt, p+1);
        }
        uint32_t af[4][4];
        #pragma unroll
        for (int mt=0;mt<4;mt++)
            *(uint4*)af[mt] = *(const uint4*)&As[buf][wm*4+mt][lane][0];
        #pragma unroll
        for (int mt=0;mt<4;mt++){
            #pragma unroll
            for (int nt=0;nt<4;nt++)
                mma16(acc[mt][nt], af[mt], bf[nt]);
        }
        if (p < 31) {
            stageA(buf^1, pa0, qa);  stageA(buf^1, pa1, qa+1);
            #pragma unroll
            for (int nt=0;nt<4;nt++){ bf[nt][0]=bfn[nt][0]; bf[nt][1]=bfn[nt][1]; }
        }
        __syncthreads();
    }

    // epilogue
    #pragma unroll
    for (int mt=0;mt<4;mt++){
        int row0 = brow + wm*64 + mt*16 + gg;
        int row1 = row0 + 8;
        float es0 = 0.f, es1 = 0.f;
        #pragma unroll
        for (int nt=0;nt<4;nt++){
            int col = bcol + wn*32 + nt*8 + 2*tt;
            float v0 = acc[mt][nt][0], v1 = acc[mt][nt][1];
            float v2 = acc[mt][nt][2], v3 = acc[mt][nt][3];
            if (EPI == 1) {
                float2 c0 = *(const float2*)(addC + (size_t)row0*HID + col);
                float2 c1 = *(const float2*)(addC + (size_t)row1*HID + col);
                v0 = c0.x + silu_f(v0); v1 = c0.y + silu_f(v1);
                v2 = c1.x + silu_f(v2); v3 = c1.y + silu_f(v3);
            }
            if (EPI == 2) {
                float2 bb = *(const float2*)(bias + col);
                float2 w2 = *(const float2*)(W2p + col);
                v0 += bb.x; v1 += bb.y; v2 += bb.x; v3 += bb.y;
                es0 += silu_f(v0)*w2.x + silu_f(v1)*w2.y;
                es1 += silu_f(v2)*w2.x + silu_f(v3)*w2.y;
            } else {
                float2 o0; o0.x=v0; o0.y=v1;
                float2 o1; o1.x=v2; o1.y=v3;
                *(float2*)(C + (size_t)row0*HID + col) = o0;
                *(float2*)(C + (size_t)row1*HID + col) = o1;
            }
        }
        if (EPI == 2) {
            atomicAdd(&g_eblk[row0], es0);
            atomicAdd(&g_eblk[row1], es1);
        }
    }
}

// ---------------- 7. fused edge/message kernel ----------------
__global__ __launch_bounds__(128) void k_edge(
    const float* __restrict__ wz_l, const float* __restrict__ eWl,
    const float* __restrict__ Zb_old, float* __restrict__ Zb_new)
{
    int d = blockIdx.x;
    int tid = threadIdx.x;
    const float4* hW4 = (const float4*)g_hW;
    float4 hd  = hW4[(size_t)d*128 + tid];
    float4 wzv = ((const float4*)wz_l)[tid];
    float4 ew0 = ((const float4*)eWl)[tid];
    float4 ew1 = ((const float4*)(eWl + HID))[tid];
    float4 ag = make_float4(0.f,0.f,0.f,0.f);

    __shared__ int   snbr[NE];
    __shared__ float sp[NE][4];
    __shared__ float sx[NE], sy[NE], sz[NE];
    if (tid < NE) snbr[tid] = g_nbr[d*NE + tid];
    __syncthreads();

    int wid = tid >> 5, lane = tid & 31;
    #pragma unroll
    for (int e = 0; e < NE; e++) {
        int s = snbr[e];
        float4 ew = (e < KNN) ? ew0 : ew1;
        float4 hs = hW4[(size_t)s*128 + tid];
        float m0 = silu_f(hs.x + hd.x + ew.x);
        float m1 = silu_f(hs.y + hd.y + ew.y);
        float m2 = silu_f(hs.z + hd.z + ew.z);
        float m3 = silu_f(hs.w + hd.w + ew.w);
        ag.x += m0; ag.y += m1; ag.z += m2; ag.w += m3;
        float p = m0*wzv.x + m1*wzv.y + m2*wzv.z + m3*wzv.w;
        #pragma unroll
        for (int off = 16; off; off >>= 1) p += __shfl_down_sync(0xffffffffu, p, off);
        if (lane == 0) sp[e][wid] = p;
    }
    __syncthreads();

    float Zdx = Zb_old[d*3+0], Zdy = Zb_old[d*3+1], Zdz = Zb_old[d*3+2];
    if (tid < NE) {
        float coef = tanhf(sp[tid][0] + sp[tid][1] + sp[tid][2] + sp[tid][3]);
        int s = snbr[tid];
        sx[tid] = (Zb_old[s*3+0] - Zdx)*coef;
        sy[tid] = (Zb_old[s*3+1] - Zdy)*coef;
        sz[tid] = (Zb_old[s*3+2] - Zdz)*coef;
    }
    __syncthreads();

    ((float4*)g_agg)[(size_t)d*128 + tid] = ag;
    if (tid == 0) {
        float zx=0.f, zy=0.f, zz=0.f;
        #pragma unroll
        for (int e = 0; e < NE; e++) { zx += sx[e]; zy += sy[e]; zz += sz[e]; }
        const float inv = 1.0f / (2*KNN);
        Zb_new[d*3+0] = Zdx + zx*inv;
        Zb_new[d*3+1] = Zdy + zy*inv;
        Zb_new[d*3+2] = Zdz + zz*inv;
    }
}

// ---------------- 8. energy reduce ----------------
__global__ __launch_bounds__(256) void k_energy(float* __restrict__ out)
{
    int g = blockIdx.x;
    int tid = threadIdx.x;
    float p = 0.f;
    #pragma unroll
    for (int k = 0; k < 4; k++) p += g_eblk[g*NBG + k*256 + tid];
    __shared__ float sred[8];
    #pragma unroll
    for (int off = 16; off; off >>= 1) p += __shfl_down_sync(0xffffffffu, p, off);
    if ((tid & 31) == 0) sred[tid >> 5] = p;
    __syncthreads();
    if (tid == 0) {
        float s = 0.f;
        #pragma unroll
        for (int w = 0; w < 8; w++) s += sred[w];
        out[OFF_E + g] = s;
        if (g == 0) out[OFF_LOSS] = 0.f;
    }
}

// ---------------- 9. graph_repr (two-phase) ----------------
__global__ __launch_bounds__(512) void k_graphp()
{
    int g = blockIdx.y;
    int chunk = blockIdx.x;
    int tid = threadIdx.x;
    float acc = 0.f;
    const float* hp = g_h + (size_t)(g*NBG + chunk*128)*HID + tid;
    for (int b = 0; b < 128; b++) acc += hp[(size_t)b*HID];
    g_gpart[(g*8 + chunk)*HID + tid] = acc;
}

__global__ __launch_bounds__(512) void k_graph2(float* __restrict__ out)
{
    int g = blockIdx.x;
    int tid = threadIdx.x;
    float acc = 0.f;
    #pragma unroll
    for (int c = 0; c < 8; c++) acc += g_gpart[(g*8 + c)*HID + tid];
    out[OFF_GR + g*HID + tid] = acc;
}

// ---------------- 10. pred_noise + loss ----------------
__global__ __launch_bounds__(256) void k_noise_loss(const float* __restrict__ noise,
                                                    float* __restrict__ out)
{
    int u = blockIdx.x*blockDim.x + threadIdx.x;
    float local = 0.f;
    if (u < NU) {
        int b = u >> 2;
        float dx = g_ZbB[b*3+0] - g_Zb0[b*3+0];
        float dy = g_ZbB[b*3+1] - g_Zb0[b*3+1];
        float dz = g_ZbB[b*3+2] - g_Zb0[b*3+2];
        out[OFF_PN + u*3+0] = dx;
        out[OFF_PN + u*3+1] = dy;
        out[OFF_PN + u*3+2] = dz;
        float ex = dx - noise[u*3+0];
        float ey = dy - noise[u*3+1];
        float ez = dz - noise[u*3+2];
        local = ex*ex + ey*ey + ez*ez;
    }
    __shared__ float sred[8];
    float p = local;
    #pragma unroll
    for (int off = 16; off; off >>= 1) p += __shfl_down_sync(0xffffffffu, p, off);
    if ((threadIdx.x & 31) == 0) sred[threadIdx.x >> 5] = p;
    __syncthreads();
    if (threadIdx.x == 0) {
        float s = 0.f;
        #pragma unroll
        for (int w = 0; w < 8; w++) s += sred[w];
        atomicAdd(out + OFF_LOSS, s * 0.0625f);
    }
}

// ---------------- 11. unit_repr & block_repr ----------------
__global__ void k_unit(float* __restrict__ out)
{
    int idx = blockIdx.x*blockDim.x + threadIdx.x;
    if (idx >= NU*(HID/4)) return;
    int u = idx >> 7;
    int c = idx & 127;
    float4 h0 = ((const float4*)g_H0)[idx];
    float4 hb = ((const float4*)g_h)[(size_t)(u>>2)*128 + c];
    float4 r; r.x=h0.x+hb.x; r.y=h0.y+hb.y; r.z=h0.z+hb.z; r.w=h0.w+hb.w;
    ((float4*)(out + OFF_UR))[idx] = r;
}

__global__ void k_brepr(float* __restrict__ out)
{
    int idx = blockIdx.x*blockDim.x + threadIdx.x;
    if (idx >= NB*(HID/4)) return;
    ((float4*)(out + OFF_BR))[idx] = ((const float4*)g_h)[idx];
}

// ---------------- launch ----------------
extern "C" void kernel_launch(void* const* d_in, const int* in_sizes, int n_in,
                              void* d_out, int out_size)
{
    const float* Z         = (const float*)d_in[0];
    const int*   B         = (const int*)  d_in[1];
    const int*   A         = (const int*)  d_in[2];
    const int*   AP        = (const int*)  d_in[3];
    const int*   seg       = (const int*)  d_in[6];
    const float* noise     = (const float*)d_in[7];
    const int*   nl        = (const int*)  d_in[8];
    const float* sigmas    = (const float*)d_in[9];
    const float* atom_emb  = (const float*)d_in[10];
    const float* pos_emb   = (const float*)d_in[11];
    const float* block_emb = (const float*)d_in[12];
    const float* edge_emb  = (const float*)d_in[13];
    const float* Wm        = (const float*)d_in[14];
    const float* We        = (const float*)d_in[15];
    const float* Wu        = (const float*)d_in[16];
    const float* wz        = (const float*)d_in[17];
    const float* W1        = (const float*)d_in[18];
    const float* b1        = (const float*)d_in[19];
    const float* W2        = (const float*)d_in[20];
    float* out = (float*)d_out;

    float *p_h, *p_hW, *p_agg, *p_ZbA, *p_ZbB, *p_eW;
    uint32_t *p_Wh;
    cudaGetSymbolAddress((void**)&p_h,   g_h);
    cudaGetSymbolAddress((void**)&p_hW,  g_hW);
    cudaGetSymbolAddress((void**)&p_agg, g_agg);
    cudaGetSymbolAddress((void**)&p_ZbA, g_ZbA);
    cudaGetSymbolAddress((void**)&p_ZbB, g_ZbB);
    cudaGetSymbolAddress((void**)&p_eW,  g_eW);
    cudaGetSymbolAddress((void**)&p_Wh,  g_Wh);

    k_perturb<<<(NB+255)/256, 256>>>(Z, noise, nl, sigmas);
    k_H0h<<<NB, 128>>>(A, AP, B, atom_emb, pos_emb, block_emb);
    k_ew<<<(LAY*2*HID+255)/256, 256>>>(edge_emb, We);
    k_wprep_h<<<dim3(32, 7), 256>>>(Wm, Wu, W1);

    k_knn_part<<<dim3(JP, 4, G), 256>>>(seg);
    k_knn_merge<<<(NB+255)/256, 256>>>();

    const size_t WSTRIDE = (size_t)32*64*32*2;
    float* zold = p_ZbA;
    float* znew = p_ZbB;
    for (int l = 0; l < LAY; l++) {
        gemm_h<0,0><<<dim3(4,64), 256>>>(p_h, p_Wh + (size_t)l*WSTRIDE,
                                         p_hW, nullptr, nullptr, nullptr);
        k_edge<<<NB, 128>>>(wz + l*HID, p_eW + l*2*HID, zold, znew);
        gemm_h<0,1><<<dim3(4,64), 256>>>(p_agg, p_Wh + (size_t)(3+l)*WSTRIDE,
                                         p_h, p_h, nullptr, nullptr);
        float* tmp = zold; zold = znew; znew = tmp;
    }
    // after 3 swaps the final Zb lives in g_ZbB

    gemm_h<1,2><<<dim3(4,64), 256>>>(p_h, p_Wh + (size_t)6*WSTRIDE,
                                     nullptr, nullptr, b1, W2);
    k_energy<<<G, 256>>>(out);
    k_graphp<<<dim3(8, G), 512>>>();
    k_graph2<<<G, 512>>>(out);
    k_noise_loss<<<(NU+255)/256, 256>>>(noise, out);
    k_unit<<<(NU*(HID/4)+255)/256, 256>>>(out);
    k_brepr<<<(NB*(HID/4)+255)/256, 256>>>(out);
}

// round 15
// speedup vs baseline: 3.6168x; 1.0693x over previous
#include <cuda_runtime.h>
#include <cuda_fp16.h>
#include <math.h>
#include <stdint.h>

#define G    8
#define NBG  1024
#define APB  4
#define HID  512
#define ES   64
#define KNN  9
#define LAY  3
#define NB   (G*NBG)        // 8192
#define NU   (NB*APB)       // 32768
#define NE   (2*KNN)        // 18 edges per dst block
#define JP   8              // knn j-partitions

// output layout (float32, concatenated reference outputs)
#define OFF_E    0
#define OFF_PN   8
#define OFF_UR   98312            // 8 + 32768*3
#define OFF_BR   16875528         // + 32768*512
#define OFF_GR   21069832         // + 8192*512
#define OFF_LOSS 21073928         // + 8*512

// ---------------- scratch (static device globals; no allocations) ----------
__device__ float4 g_ZpS[NU];
__device__ float  g_H0[NU*HID];
__device__ float  g_h[NB*HID];
__device__ float  g_hW[NB*HID];
__device__ float  g_Zb0[NB*3];
__device__ float  g_ZbA[NB*3];
__device__ float  g_ZbB[NB*3];
__device__ int    g_nbr[NB*NE];
__device__ float  g_eW[LAY*2*HID];
__device__ float  g_eblk[NB];
__device__ float  g_gpart[G*8*HID];
__device__ float  g_pD[NB*JP*2*KNN];
__device__ int    g_pI[NB*JP*2*KNN];
__device__ uint32_t g_Wh[7*32*64*32*2];      // 7 weights, fp16 B-fragment order
__device__ uint32_t g_hf[(NB/16)*32*32*4];   // h as fp16 A-fragments
__device__ uint32_t g_aggf[(NB/16)*32*32*4]; // agg as fp16 A-fragments
__device__ uint32_t g_shf[(NB/16)*32*32*4];  // silu(h) as fp16 A-fragments

__device__ __forceinline__ float silu_f(float x){ return x / (1.0f + expf(-x)); }

__device__ __forceinline__ void mma16(float* d, const uint32_t* a, const uint32_t* b){
    asm volatile("mma.sync.aligned.m16n8k16.row.col.f32.f16.f16.f32 "
        "{%0,%1,%2,%3}, {%4,%5,%6,%7}, {%8,%9}, {%0,%1,%2,%3};"
        : "+f"(d[0]), "+f"(d[1]), "+f"(d[2]), "+f"(d[3])
        : "r"(a[0]), "r"(a[1]), "r"(a[2]), "r"(a[3]), "r"(b[0]), "r"(b[1]));
}

__device__ __forceinline__ uint32_t pack_h2(float lo, float hi){
    __half2 h = __floats2half2_rn(lo, hi);
    return *(uint32_t*)&h;
}

// store an fp16 pair (cols col, col+1 of row) into A-fragment layout
// layout: [mtile][kp][lane][reg]; lane = (row&7)*4 + ((col&7)>>1); reg = ((row&15)>>3) + 2*((col&15)>>3)
__device__ __forceinline__ void store_frag(uint32_t* base, int row, int col, float lo, float hi){
    int mt = row >> 4, rr = row & 15;
    int kp = col >> 4, kk = col & 15;
    int lane = (rr & 7)*4 + ((kk & 7) >> 1);
    int reg  = (rr >> 3) + 2*(kk >> 3);
    base[(((size_t)mt*32 + kp)*32 + lane)*4 + reg] = pack_h2(lo, hi);
}

// ---------------- 1. perturb + sq + block means + eblk zero ----------------
__global__ void k_perturb(const float* __restrict__ Z, const float* __restrict__ noise,
                          const int* __restrict__ nl, const float* __restrict__ sigmas)
{
    int b = blockIdx.x*blockDim.x + threadIdx.x;
    if (b >= NB) return;
    int g = b >> 10;
    float s = sigmas[nl[g]];
    float mx=0.f, my=0.f, mz=0.f;
    #pragma unroll
    for (int a = 0; a < 4; a++) {
        int u = b*4 + a;
        float x = Z[u*3+0] + noise[u*3+0]*s;
        float y = Z[u*3+1] + noise[u*3+1]*s;
        float z = Z[u*3+2] + noise[u*3+2]*s;
        float4 v; v.x=x; v.y=y; v.z=z; v.w = x*x + y*y + z*z;
        g_ZpS[u] = v;
        mx += x; my += y; mz += z;
    }
    mx *= 0.25f; my *= 0.25f; mz *= 0.25f;
    g_Zb0[b*3+0]=mx; g_Zb0[b*3+1]=my; g_Zb0[b*3+2]=mz;
    g_ZbA[b*3+0]=mx; g_ZbA[b*3+1]=my; g_ZbA[b*3+2]=mz;
    g_eblk[b] = 0.f;
}

// ---------------- 2. fused H0 + block mean h (+h frags) ----------------
__global__ __launch_bounds__(128) void k_H0h(const int* __restrict__ A, const int* __restrict__ P,
                     const int* __restrict__ B,
                     const float* __restrict__ ae, const float* __restrict__ pe,
                     const float* __restrict__ be)
{
    int b = blockIdx.x;
    int c = threadIdx.x;
    const float4* ae4 = (const float4*)ae;
    const float4* pe4 = (const float4*)pe;
    const float4* be4 = (const float4*)be;
    float4 bb = be4[B[b]*128 + c];
    float sx=0.f, sy=0.f, sz=0.f, sw=0.f;
    #pragma unroll
    for (int a = 0; a < 4; a++) {
        int u = b*4 + a;
        float4 av = ae4[A[u]*128 + c];
        float4 pv = pe4[P[u]*128 + c];
        float4 r;
        r.x = av.x + pv.x + bb.x;
        r.y = av.y + pv.y + bb.y;
        r.z = av.z + pv.z + bb.z;
        r.w = av.w + pv.w + bb.w;
        ((float4*)g_H0)[(size_t)u*128 + c] = r;
        sx += r.x; sy += r.y; sz += r.z; sw += r.w;
    }
    float4 hm; hm.x = sx*0.25f; hm.y = sy*0.25f; hm.z = sz*0.25f; hm.w = sw*0.25f;
    ((float4*)g_h)[(size_t)b*128 + c] = hm;
    store_frag(g_hf, b, 4*c,   hm.x, hm.y);
    store_frag(g_hf, b, 4*c+2, hm.z, hm.w);
}

// ---------------- 3. eW precompute ----------------
__global__ void k_ew(const float* __restrict__ ee, const float* __restrict__ We)
{
    int idx = blockIdx.x*blockDim.x + threadIdx.x;
    if (idx >= LAY*2*HID) return;
    int l = idx / (2*HID);
    int r = idx % (2*HID);
    int t = r / HID;
    int c = r % HID;
    float acc = 0.f;
    #pragma unroll 8
    for (int k = 0; k < ES; k++)
        acc += ee[t*ES+k] * We[(l*ES+k)*HID + c];
    g_eW[idx] = acc;
}

// ---------------- 4. weight prep: fp16 B-fragment layout ----------------
__global__ __launch_bounds__(256) void k_wprep_h(const float* __restrict__ Wm,
                                                 const float* __restrict__ Wu,
                                                 const float* __restrict__ W1)
{
    int kp = blockIdx.x, w = blockIdx.y;
    const float* W = (w < 3) ? (Wm + (size_t)w*HID*HID)
                   : (w < 6) ? (Wu + (size_t)(w-3)*HID*HID)
                             : W1;
    uint32_t* dst = g_Wh + (((size_t)w*32 + kp)*64*32*2);
    for (int i = threadIdx.x; i < 64*32*2; i += 256) {
        int ntg  = i >> 6;
        int rem  = i & 63;
        int lane = rem >> 1;
        int reg  = rem & 1;
        int k = kp*16 + reg*8 + 2*(lane & 3);
        int n = ntg*8 + (lane >> 2);
        float lo = W[(size_t)k*HID + n];
        float hi = W[(size_t)(k+1)*HID + n];
        dst[i] = pack_h2(lo, hi);
    }
}

// ---------------- 5. KNN ----------------
__device__ __forceinline__ void ins9(float D, int j, float* bd, int* bi)
{
    if (D >= bd[8]) return;
    int p = 8;
    while (p > 0 && bd[p-1] > D) { bd[p]=bd[p-1]; bi[p]=bi[p-1]; --p; }
    bd[p]=D; bi[p]=j;
}

__device__ __forceinline__ void ins9lex(float D, int i, float* bd, int* bi)
{
    if (D > bd[8] || (D == bd[8] && i >= bi[8])) return;
    int p = 8;
    while (p > 0 && (bd[p-1] > D || (bd[p-1] == D && bi[p-1] > i))) {
        bd[p]=bd[p-1]; bi[p]=bi[p-1]; --p;
    }
    bd[p]=D; bi[p]=i;
}

#define JBL (NBG/JP)    // 128 blocks per j-partition

__global__ __launch_bounds__(256) void k_knn_part(const int* __restrict__ seg)
{
    __shared__ float4 sa[JBL*APB];
    __shared__ int sseg[JBL];
    int part  = blockIdx.x;
    int chunk = blockIdx.y;
    int g     = blockIdx.z;
    int jbase = part*JBL;
    int abase = g*NBG*APB + jbase*APB;
    for (int i = threadIdx.x; i < JBL*APB; i += 256) sa[i] = g_ZpS[abase + i];
    if (threadIdx.x < JBL) sseg[threadIdx.x] = seg[g*NBG + jbase + threadIdx.x];
    __syncthreads();

    int ib = chunk*256 + threadIdx.x;
    int gd = g*NBG + ib;
    float4 o0 = g_ZpS[gd*4+0], o1 = g_ZpS[gd*4+1], o2 = g_ZpS[gd*4+2], o3 = g_ZpS[gd*4+3];
    int myseg = seg[gd];

    float bd0[KNN], bd1[KNN]; int bi0[KNN], bi1[KNN];
    #pragma unroll
    for (int k = 0; k < KNN; k++) { bd0[k]=3.0e38f; bd1[k]=3.0e38f; bi0[k]=0x3fffffff; bi1[k]=0x3fffffff; }

    for (int jj = 0; jj < JBL; jj++) {
        float4 c0 = sa[jj*4+0], c1 = sa[jj*4+1], c2 = sa[jj*4+2], c3 = sa[jj*4+3];
        #define DD(o,c) ((o).w + (c).w - 2.0f*((o).x*(c).x + (o).y*(c).y + (o).z*(c).z))
        float d = DD(o0,c0);
        d = fminf(d, DD(o0,c1)); d = fminf(d, DD(o0,c2)); d = fminf(d, DD(o0,c3));
        d = fminf(d, DD(o1,c0)); d = fminf(d, DD(o1,c1)); d = fminf(d, DD(o1,c2)); d = fminf(d, DD(o1,c3));
        d = fminf(d, DD(o2,c0)); d = fminf(d, DD(o2,c1)); d = fminf(d, DD(o2,c2)); d = fminf(d, DD(o2,c3));
        d = fminf(d, DD(o3,c0)); d = fminf(d, DD(o3,c1)); d = fminf(d, DD(o3,c2)); d = fminf(d, DD(o3,c3));
        #undef DD
        int j = jbase + jj;
        if (sseg[jj] == myseg) {
            if (j != ib) ins9(d, j, bd0, bi0);
        } else {
            ins9(d, j, bd1, bi1);
        }
    }
    size_t base = ((size_t)gd*JP + part)*2*KNN;
    #pragma unroll
    for (int k = 0; k < KNN; k++) {
        g_pD[base + k] = bd0[k];          g_pI[base + k] = bi0[k];
        g_pD[base + KNN + k] = bd1[k];    g_pI[base + KNN + k] = bi1[k];
    }
}

__global__ void k_knn_merge()
{
    int b = blockIdx.x*blockDim.x + threadIdx.x;
    if (b >= NB) return;
    int goff = (b >> 10) * NBG;
    #pragma unroll
    for (int list = 0; list < 2; list++) {
        float od[KNN]; int oi[KNN];
        #pragma unroll
        for (int k = 0; k < KNN; k++) { od[k]=3.1e38f; oi[k]=0x7fffffff; }
        for (int part = 0; part < JP; part++) {
            size_t base = ((size_t)b*JP + part)*2*KNN + list*KNN;
            #pragma unroll
            for (int k = 0; k < KNN; k++)
                ins9lex(g_pD[base+k], g_pI[base+k], od, oi);
        }
        #pragma unroll
        for (int k = 0; k < KNN; k++)
            g_nbr[b*NE + list*KNN + k] = goff + oi[k];
    }
}

// ---------------- 6. fragment-direct fp16 tensor GEMM ----------------------
// C[8192,512] = A @ W, with A pre-packed fp16 A-frags and W fp16 B-frags.
// No smem, no __syncthreads. 128x128 CTA tile, 8 warps (2x4), BK=16.
// EPI 0: C = acc (fp32)
// EPI 1: C = addC + silu(acc) (fp32) + A-frag image of C (+ silu frags if WSILU)
// EPI 2: energy head — atomicAdd_row( silu(acc+bias)·W2 ), no C store.
template<int EPI, int WSILU>
__global__ __launch_bounds__(256) void gemm_f(
    const uint32_t* __restrict__ Af, const uint32_t* __restrict__ Bh,
    float* __restrict__ C, const float* __restrict__ addC,
    const float* __restrict__ bias, const float* __restrict__ W2p)
{
    const int tid  = threadIdx.x;
    const int lane = tid & 31, wid = tid >> 5;
    const int wm = wid >> 2, wn = wid & 3;
    const int brow = blockIdx.y*128;
    const int bcol = blockIdx.x*128;
    const int gg = lane >> 2, tt = lane & 3;

    float acc[4][4][4];
    #pragma unroll
    for (int mt=0;mt<4;mt++){
        #pragma unroll
        for (int nt=0;nt<4;nt++){
            #pragma unroll
            for (int r=0;r<4;r++) acc[mt][nt][r]=0.f;
        }
    }

    // A frags: [(gmt*32+kp)*32+lane]*4, gmt = blockIdx.y*8 + wm*4 + mt
    const uint32_t* aBase = Af + (((size_t)(blockIdx.y*8 + wm*4)*32)*32 + lane)*4;
    // per mt offset: mt*32*32*4 = mt*4096; per kp: 32*4 = 128
    const uint32_t* bBase = Bh + (((size_t)(blockIdx.x*16 + wn*4))*32 + lane)*2;
    // per nt offset: 32*2 = 64; per kp: 64*32*2 = 4096

    uint4 a[4]; uint2 b[4];
    uint4 an[4]; uint2 bn[4];
    #pragma unroll
    for (int mt=0;mt<4;mt++) a[mt] = *(const uint4*)(aBase + mt*4096);
    #pragma unroll
    for (int nt=0;nt<4;nt++) b[nt] = *(const uint2*)(bBase + nt*64);

    for (int p = 0; p < 32; p++) {
        if (p < 31) {
            #pragma unroll
            for (int mt=0;mt<4;mt++) an[mt] = *(const uint4*)(aBase + (p+1)*128 + mt*4096);
            #pragma unroll
            for (int nt=0;nt<4;nt++) bn[nt] = *(const uint2*)(bBase + (size_t)(p+1)*4096 + nt*64);
        }
        #pragma unroll
        for (int mt=0;mt<4;mt++){
            #pragma unroll
            for (int nt=0;nt<4;nt++)
                mma16(acc[mt][nt], (const uint32_t*)&a[mt], (const uint32_t*)&b[nt]);
        }
        if (p < 31) {
            #pragma unroll
            for (int mt=0;mt<4;mt++) a[mt] = an[mt];
            #pragma unroll
            for (int nt=0;nt<4;nt++) b[nt] = bn[nt];
        }
    }

    // epilogue
    #pragma unroll
    for (int mt=0;mt<4;mt++){
        int row0 = brow + wm*64 + mt*16 + gg;
        int row1 = row0 + 8;
        float es0 = 0.f, es1 = 0.f;
        #pragma unroll
        for (int nt=0;nt<4;nt++){
            int col = bcol + wn*32 + nt*8 + 2*tt;
            float v0 = acc[mt][nt][0], v1 = acc[mt][nt][1];
            float v2 = acc[mt][nt][2], v3 = acc[mt][nt][3];
            if (EPI == 1) {
                float2 c0 = *(const float2*)(addC + (size_t)row0*HID + col);
                float2 c1 = *(const float2*)(addC + (size_t)row1*HID + col);
                v0 = c0.x + silu_f(v0); v1 = c0.y + silu_f(v1);
                v2 = c1.x + silu_f(v2); v3 = c1.y + silu_f(v3);
                store_frag(g_hf, row0, col, v0, v1);
                store_frag(g_hf, row1, col, v2, v3);
                if (WSILU) {
                    store_frag(g_shf, row0, col, silu_f(v0), silu_f(v1));
                    store_frag(g_shf, row1, col, silu_f(v2), silu_f(v3));
                }
            }
            if (EPI == 2) {
                float2 bb = *(const float2*)(bias + col);
                float2 w2 = *(const float2*)(W2p + col);
                v0 += bb.x; v1 += bb.y; v2 += bb.x; v3 += bb.y;
                es0 += silu_f(v0)*w2.x + silu_f(v1)*w2.y;
                es1 += silu_f(v2)*w2.x + silu_f(v3)*w2.y;
            } else {
                float2 o0; o0.x=v0; o0.y=v1;
                float2 o1; o1.x=v2; o1.y=v3;
                *(float2*)(C + (size_t)row0*HID + col) = o0;
                *(float2*)(C + (size_t)row1*HID + col) = o1;
            }
        }
        if (EPI == 2) {
            atomicAdd(&g_eblk[row0], es0);
            atomicAdd(&g_eblk[row1], es1);
        }
    }
}

// ---------------- 7. fused edge/message kernel (agg -> frags) --------------
__global__ __launch_bounds__(128) void k_edge(
    const float* __restrict__ wz_l, const float* __restrict__ eWl,
    const float* __restrict__ Zb_old, float* __restrict__ Zb_new)
{
    int d = blockIdx.x;
    int tid = threadIdx.x;
    const float4* hW4 = (const float4*)g_hW;
    float4 hd  = hW4[(size_t)d*128 + tid];
    float4 wzv = ((const float4*)wz_l)[tid];
    float4 ew0 = ((const float4*)eWl)[tid];
    float4 ew1 = ((const float4*)(eWl + HID))[tid];
    float4 ag = make_float4(0.f,0.f,0.f,0.f);

    __shared__ int   snbr[NE];
    __shared__ float sp[NE][4];
    __shared__ float sx[NE], sy[NE], sz[NE];
    if (tid < NE) snbr[tid] = g_nbr[d*NE + tid];
    __syncthreads();

    int wid = tid >> 5, lane = tid & 31;
    #pragma unroll
    for (int e = 0; e < NE; e++) {
        int s = snbr[e];
        float4 ew = (e < KNN) ? ew0 : ew1;
        float4 hs = hW4[(size_t)s*128 + tid];
        float m0 = silu_f(hs.x + hd.x + ew.x);
        float m1 = silu_f(hs.y + hd.y + ew.y);
        float m2 = silu_f(hs.z + hd.z + ew.z);
        float m3 = silu_f(hs.w + hd.w + ew.w);
        ag.x += m0; ag.y += m1; ag.z += m2; ag.w += m3;
        float p = m0*wzv.x + m1*wzv.y + m2*wzv.z + m3*wzv.w;
        #pragma unroll
        for (int off = 16; off; off >>= 1) p += __shfl_down_sync(0xffffffffu, p, off);
        if (lane == 0) sp[e][wid] = p;
    }
    __syncthreads();

    float Zdx = Zb_old[d*3+0], Zdy = Zb_old[d*3+1], Zdz = Zb_old[d*3+2];
    if (tid < NE) {
        float coef = tanhf(sp[tid][0] + sp[tid][1] + sp[tid][2] + sp[tid][3]);
        int s = snbr[tid];
        sx[tid] = (Zb_old[s*3+0] - Zdx)*coef;
        sy[tid] = (Zb_old[s*3+1] - Zdy)*coef;
        sz[tid] = (Zb_old[s*3+2] - Zdz)*coef;
    }
    __syncthreads();

    store_frag(g_aggf, d, 4*tid,   ag.x, ag.y);
    store_frag(g_aggf, d, 4*tid+2, ag.z, ag.w);
    if (tid == 0) {
        float zx=0.f, zy=0.f, zz=0.f;
        #pragma unroll
        for (int e = 0; e < NE; e++) { zx += sx[e]; zy += sy[e]; zz += sz[e]; }
        const float inv = 1.0f / (2*KNN);
        Zb_new[d*3+0] = Zdx + zx*inv;
        Zb_new[d*3+1] = Zdy + zy*inv;
        Zb_new[d*3+2] = Zdz + zz*inv;
    }
}

// ---------------- 8. energy reduce ----------------
__global__ __launch_bounds__(256) void k_energy(float* __restrict__ out)
{
    int g = blockIdx.x;
    int tid = threadIdx.x;
    float p = 0.f;
    #pragma unroll
    for (int k = 0; k < 4; k++) p += g_eblk[g*NBG + k*256 + tid];
    __shared__ float sred[8];
    #pragma unroll
    for (int off = 16; off; off >>= 1) p += __shfl_down_sync(0xffffffffu, p, off);
    if ((tid & 31) == 0) sred[tid >> 5] = p;
    __syncthreads();
    if (tid == 0) {
        float s = 0.f;
        #pragma unroll
        for (int w = 0; w < 8; w++) s += sred[w];
        out[OFF_E + g] = s;
        if (g == 0) out[OFF_LOSS] = 0.f;
    }
}

// ---------------- 9. graph_repr (two-phase) ----------------
__global__ __launch_bounds__(512) void k_graphp()
{
    int g = blockIdx.y;
    int chunk = blockIdx.x;
    int tid = threadIdx.x;
    float acc = 0.f;
    const float* hp = g_h + (size_t)(g*NBG + chunk*128)*HID + tid;
    for (int b = 0; b < 128; b++) acc += hp[(size_t)b*HID];
    g_gpart[(g*8 + chunk)*HID + tid] = acc;
}

__global__ __launch_bounds__(512) void k_graph2(float* __restrict__ out)
{
    int g = blockIdx.x;
    int tid = threadIdx.x;
    float acc = 0.f;
    #pragma unroll
    for (int c = 0; c < 8; c++) acc += g_gpart[(g*8 + c)*HID + tid];
    out[OFF_GR + g*HID + tid] = acc;
}

// ---------------- 10. pred_noise + loss ----------------
__global__ __launch_bounds__(256) void k_noise_loss(const float* __restrict__ noise,
                                                    float* __restrict__ out)
{
    int u = blockIdx.x*blockDim.x + threadIdx.x;
    float local = 0.f;
    if (u < NU) {
        int b = u >> 2;
        float dx = g_ZbB[b*3+0] - g_Zb0[b*3+0];
        float dy = g_ZbB[b*3+1] - g_Zb0[b*3+1];
        float dz = g_ZbB[b*3+2] - g_Zb0[b*3+2];
        out[OFF_PN + u*3+0] = dx;
        out[OFF_PN + u*3+1] = dy;
        out[OFF_PN + u*3+2] = dz;
        float ex = dx - noise[u*3+0];
        float ey = dy - noise[u*3+1];
        float ez = dz - noise[u*3+2];
        local = ex*ex + ey*ey + ez*ez;
    }
    __shared__ float sred[8];
    float p = local;
    #pragma unroll
    for (int off = 16; off; off >>= 1) p += __shfl_down_sync(0xffffffffu, p, off);
    if ((threadIdx.x & 31) == 0) sred[threadIdx.x >> 5] = p;
    __syncthreads();
    if (threadIdx.x == 0) {
        float s = 0.f;
        #pragma unroll
        for (int w = 0; w < 8; w++) s += sred[w];
        atomicAdd(out + OFF_LOSS, s * 0.0625f);
    }
}

// ---------------- 11. unit_repr & block_repr ----------------
__global__ void k_unit(float* __restrict__ out)
{
    int idx = blockIdx.x*blockDim.x + threadIdx.x;
    if (idx >= NU*(HID/4)) return;
    int u = idx >> 7;
    int c = idx & 127;
    float4 h0 = ((const float4*)g_H0)[idx];
    float4 hb = ((const float4*)g_h)[(size_t)(u>>2)*128 + c];
    float4 r; r.x=h0.x+hb.x; r.y=h0.y+hb.y; r.z=h0.z+hb.z; r.w=h0.w+hb.w;
    ((float4*)(out + OFF_UR))[idx] = r;
}

__global__ void k_brepr(float* __restrict__ out)
{
    int idx = blockIdx.x*blockDim.x + threadIdx.x;
    if (idx >= NB*(HID/4)) return;
    ((float4*)(out + OFF_BR))[idx] = ((const float4*)g_h)[idx];
}

// ---------------- launch ----------------
extern "C" void kernel_launch(void* const* d_in, const int* in_sizes, int n_in,
                              void* d_out, int out_size)
{
    const float* Z         = (const float*)d_in[0];
    const int*   B         = (const int*)  d_in[1];
    const int*   A         = (const int*)  d_in[2];
    const int*   AP        = (const int*)  d_in[3];
    const int*   seg       = (const int*)  d_in[6];
    const float* noise     = (const float*)d_in[7];
    const int*   nl        = (const int*)  d_in[8];
    const float* sigmas    = (const float*)d_in[9];
    const float* atom_emb  = (const float*)d_in[10];
    const float* pos_emb   = (const float*)d_in[11];
    const float* block_emb = (const float*)d_in[12];
    const float* edge_emb  = (const float*)d_in[13];
    const float* Wm        = (const float*)d_in[14];
    const float* We        = (const float*)d_in[15];
    const float* Wu        = (const float*)d_in[16];
    const float* wz        = (const float*)d_in[17];
    const float* W1        = (const float*)d_in[18];
    const float* b1        = (const float*)d_in[19];
    const float* W2        = (const float*)d_in[20];
    float* out = (float*)d_out;

    float *p_h, *p_hW, *p_ZbA, *p_ZbB, *p_eW;
    uint32_t *p_Wh, *p_hf, *p_aggf, *p_shf;
    cudaGetSymbolAddress((void**)&p_h,    g_h);
    cudaGetSymbolAddress((void**)&p_hW,   g_hW);
    cudaGetSymbolAddress((void**)&p_ZbA,  g_ZbA);
    cudaGetSymbolAddress((void**)&p_ZbB,  g_ZbB);
    cudaGetSymbolAddress((void**)&p_eW,   g_eW);
    cudaGetSymbolAddress((void**)&p_Wh,   g_Wh);
    cudaGetSymbolAddress((void**)&p_hf,   g_hf);
    cudaGetSymbolAddress((void**)&p_aggf, g_aggf);
    cudaGetSymbolAddress((void**)&p_shf,  g_shf);

    k_perturb<<<(NB+255)/256, 256>>>(Z, noise, nl, sigmas);
    k_H0h<<<NB, 128>>>(A, AP, B, atom_emb, pos_emb, block_emb);
    k_ew<<<(LAY*2*HID+255)/256, 256>>>(edge_emb, We);
    k_wprep_h<<<dim3(32, 7), 256>>>(Wm, Wu, W1);

    k_knn_part<<<dim3(JP, 4, G), 256>>>(seg);
    k_knn_merge<<<(NB+255)/256, 256>>>();

    const size_t WSTRIDE = (size_t)32*64*32*2;
    float* zold = p_ZbA;
    float* znew = p_ZbB;
    for (int l = 0; l < LAY; l++) {
        gemm_f<0,0><<<dim3(4,64), 256>>>(p_hf, p_Wh + (size_t)l*WSTRIDE,
                                         p_hW, nullptr, nullptr, nullptr);
        k_edge<<<NB, 128>>>(wz + l*HID, p_eW + l*2*HID, zold, znew);
        if (l < LAY-1)
            gemm_f<1,0><<<dim3(4,64), 256>>>(p_aggf, p_Wh + (size_t)(3+l)*WSTRIDE,
                                             p_h, p_h, nullptr, nullptr);
        else
            gemm_f<1,1><<<dim3(4,64), 256>>>(p_aggf, p_Wh + (size_t)(3+l)*WSTRIDE,
                                             p_h, p_h, nullptr, nullptr);
        float* tmp = zold; zold = znew; znew = tmp;
    }
    // after 3 swaps the final Zb lives in g_ZbB

    gemm_f<2,0><<<dim3(4,64), 256>>>(p_shf, p_Wh + (size_t)6*WSTRIDE,
                                     nullptr, nullptr, b1, W2);
    k_energy<<<G, 256>>>(out);
    k_graphp<<<dim3(8, G), 512>>>();
    k_graph2<<<G, 512>>>(out);
    k_noise_loss<<<(NU+255)/256, 256>>>(noise, out);
    k_unit<<<(NU*(HID/4)+255)/256, 256>>>(out);
    k_brepr<<<(NB*(HID/4)+255)/256, 256>>>(out);
}

// round 17
// speedup vs baseline: 3.6601x; 1.0120x over previous
#include <cuda_runtime.h>
#include <cuda_fp16.h>
#include <math.h>
#include <stdint.h>

#define G    8
#define NBG  1024
#define APB  4
#define HID  512
#define ES   64
#define KNN  9
#define LAY  3
#define NB   (G*NBG)        // 8192
#define NU   (NB*APB)       // 32768
#define NE   (2*KNN)        // 18 edges per dst block
#define JP   8              // knn j-partitions

// output layout (float32, concatenated reference outputs)
#define OFF_E    0
#define OFF_PN   8
#define OFF_UR   98312            // 8 + 32768*3
#define OFF_BR   16875528         // + 32768*512
#define OFF_GR   21069832         // + 8192*512
#define OFF_LOSS 21073928         // + 8*512

// ---------------- scratch (static device globals; no allocations) ----------
__device__ float4 g_ZpS[NU];
__device__ float  g_H0[NU*HID];
__device__ float  g_h[NB*HID];
__device__ float  g_hW[NB*HID];
__device__ float  g_Zb0[NB*3];
__device__ float  g_ZbA[NB*3];
__device__ float  g_ZbB[NB*3];
__device__ int    g_nbr[NB*NE];
__device__ float  g_eW[LAY*2*HID];
__device__ float  g_eblk[NB];
__device__ float  g_gpart[G*8*HID];
__device__ float  g_pD[NB*JP*2*KNN];
__device__ int    g_pI[NB*JP*2*KNN];
__device__ uint32_t g_Wh[7*32*64*32*2];      // 7 weights, fp16 B-fragment order
__device__ uint32_t g_hf[(NB/16)*32*32*4];   // h as fp16 A-fragments
__device__ uint32_t g_aggf[(NB/16)*32*32*4]; // agg as fp16 A-fragments
__device__ uint32_t g_shf[(NB/16)*32*32*4];  // silu(h) as fp16 A-fragments

__device__ __forceinline__ float silu_f(float x){ return x / (1.0f + expf(-x)); }

__device__ __forceinline__ void mma16(float* d, const uint32_t* a, const uint32_t* b){
    asm volatile("mma.sync.aligned.m16n8k16.row.col.f32.f16.f16.f32 "
        "{%0,%1,%2,%3}, {%4,%5,%6,%7}, {%8,%9}, {%0,%1,%2,%3};"
        : "+f"(d[0]), "+f"(d[1]), "+f"(d[2]), "+f"(d[3])
        : "r"(a[0]), "r"(a[1]), "r"(a[2]), "r"(a[3]), "r"(b[0]), "r"(b[1]));
}

__device__ __forceinline__ uint32_t pack_h2(float lo, float hi){
    __half2 h = __floats2half2_rn(lo, hi);
    return *(uint32_t*)&h;
}

__device__ __forceinline__ void cpa16(uint32_t dst, const void* src){
    asm volatile("cp.async.cg.shared.global [%0], [%1], 16;" :: "r"(dst), "l"(src) : "memory");
}

// store an fp16 pair (cols col, col+1 of row) into A-fragment layout
// layout: [mtile][kp][lane][reg]; lane = (row&7)*4 + ((col&7)>>1); reg = ((row&15)>>3) + 2*((col&15)>>3)
__device__ __forceinline__ void store_frag(uint32_t* base, int row, int col, float lo, float hi){
    int mt = row >> 4, rr = row & 15;
    int kp = col >> 4, kk = col & 15;
    int lane = (rr & 7)*4 + ((kk & 7) >> 1);
    int reg  = (rr >> 3) + 2*(kk >> 3);
    base[(((size_t)mt*32 + kp)*32 + lane)*4 + reg] = pack_h2(lo, hi);
}

// ---------------- 1. perturb + sq + block means + eblk zero ----------------
__global__ void k_perturb(const float* __restrict__ Z, const float* __restrict__ noise,
                          const int* __restrict__ nl, const float* __restrict__ sigmas)
{
    int b = blockIdx.x*blockDim.x + threadIdx.x;
    if (b >= NB) return;
    int g = b >> 10;
    float s = sigmas[nl[g]];
    float mx=0.f, my=0.f, mz=0.f;
    #pragma unroll
    for (int a = 0; a < 4; a++) {
        int u = b*4 + a;
        float x = Z[u*3+0] + noise[u*3+0]*s;
        float y = Z[u*3+1] + noise[u*3+1]*s;
        float z = Z[u*3+2] + noise[u*3+2]*s;
        float4 v; v.x=x; v.y=y; v.z=z; v.w = x*x + y*y + z*z;
        g_ZpS[u] = v;
        mx += x; my += y; mz += z;
    }
    mx *= 0.25f; my *= 0.25f; mz *= 0.25f;
    g_Zb0[b*3+0]=mx; g_Zb0[b*3+1]=my; g_Zb0[b*3+2]=mz;
    g_ZbA[b*3+0]=mx; g_ZbA[b*3+1]=my; g_ZbA[b*3+2]=mz;
    g_eblk[b] = 0.f;
}

// ---------------- 2. fused H0 + block mean h (+h frags) ----------------
__global__ __launch_bounds__(128) void k_H0h(const int* __restrict__ A, const int* __restrict__ P,
                     const int* __restrict__ B,
                     const float* __restrict__ ae, const float* __restrict__ pe,
                     const float* __restrict__ be)
{
    int b = blockIdx.x;
    int c = threadIdx.x;
    const float4* ae4 = (const float4*)ae;
    const float4* pe4 = (const float4*)pe;
    const float4* be4 = (const float4*)be;
    float4 bb = be4[B[b]*128 + c];
    float sx=0.f, sy=0.f, sz=0.f, sw=0.f;
    #pragma unroll
    for (int a = 0; a < 4; a++) {
        int u = b*4 + a;
        float4 av = ae4[A[u]*128 + c];
        float4 pv = pe4[P[u]*128 + c];
        float4 r;
        r.x = av.x + pv.x + bb.x;
        r.y = av.y + pv.y + bb.y;
        r.z = av.z + pv.z + bb.z;
        r.w = av.w + pv.w + bb.w;
        ((float4*)g_H0)[(size_t)u*128 + c] = r;
        sx += r.x; sy += r.y; sz += r.z; sw += r.w;
    }
    float4 hm; hm.x = sx*0.25f; hm.y = sy*0.25f; hm.z = sz*0.25f; hm.w = sw*0.25f;
    ((float4*)g_h)[(size_t)b*128 + c] = hm;
    store_frag(g_hf, b, 4*c,   hm.x, hm.y);
    store_frag(g_hf, b, 4*c+2, hm.z, hm.w);
}

// ---------------- 3. eW precompute ----------------
__global__ void k_ew(const float* __restrict__ ee, const float* __restrict__ We)
{
    int idx = blockIdx.x*blockDim.x + threadIdx.x;
    if (idx >= LAY*2*HID) return;
    int l = idx / (2*HID);
    int r = idx % (2*HID);
    int t = r / HID;
    int c = r % HID;
    float acc = 0.f;
    #pragma unroll 8
    for (int k = 0; k < ES; k++)
        acc += ee[t*ES+k] * We[(l*ES+k)*HID + c];
    g_eW[idx] = acc;
}

// ---------------- 4. weight prep: fp16 B-fragment layout ----------------
__global__ __launch_bounds__(256) void k_wprep_h(const float* __restrict__ Wm,
                                                 const float* __restrict__ Wu,
                                                 const float* __restrict__ W1)
{
    int kp = blockIdx.x, w = blockIdx.y;
    const float* W = (w < 3) ? (Wm + (size_t)w*HID*HID)
                   : (w < 6) ? (Wu + (size_t)(w-3)*HID*HID)
                             : W1;
    uint32_t* dst = g_Wh + (((size_t)w*32 + kp)*64*32*2);
    for (int i = threadIdx.x; i < 64*32*2; i += 256) {
        int ntg  = i >> 6;
        int rem  = i & 63;
        int lane = rem >> 1;
        int reg  = rem & 1;
        int k = kp*16 + reg*8 + 2*(lane & 3);
        int n = ntg*8 + (lane >> 2);
        float lo = W[(size_t)k*HID + n];
        float hi = W[(size_t)(k+1)*HID + n];
        dst[i] = pack_h2(lo, hi);
    }
}

// ---------------- 5. KNN ----------------
__device__ __forceinline__ void ins9(float D, int j, float* bd, int* bi)
{
    if (D >= bd[8]) return;
    int p = 8;
    while (p > 0 && bd[p-1] > D) { bd[p]=bd[p-1]; bi[p]=bi[p-1]; --p; }
    bd[p]=D; bi[p]=j;
}

__device__ __forceinline__ void ins9lex(float D, int i, float* bd, int* bi)
{
    if (D > bd[8] || (D == bd[8] && i >= bi[8])) return;
    int p = 8;
    while (p > 0 && (bd[p-1] > D || (bd[p-1] == D && bi[p-1] > i))) {
        bd[p]=bd[p-1]; bi[p]=bi[p-1]; --p;
    }
    bd[p]=D; bi[p]=i;
}

#define JBL (NBG/JP)    // 128 blocks per j-partition

__global__ __launch_bounds__(256) void k_knn_part(const int* __restrict__ seg)
{
    __shared__ float4 sa[JBL*APB];
    __shared__ int sseg[JBL];
    int part  = blockIdx.x;
    int chunk = blockIdx.y;
    int g     = blockIdx.z;
    int jbase = part*JBL;
    int abase = g*NBG*APB + jbase*APB;
    for (int i = threadIdx.x; i < JBL*APB; i += 256) sa[i] = g_ZpS[abase + i];
    if (threadIdx.x < JBL) sseg[threadIdx.x] = seg[g*NBG + jbase + threadIdx.x];
    __syncthreads();

    int ib = chunk*256 + threadIdx.x;
    int gd = g*NBG + ib;
    float4 o0 = g_ZpS[gd*4+0], o1 = g_ZpS[gd*4+1], o2 = g_ZpS[gd*4+2], o3 = g_ZpS[gd*4+3];
    int myseg = seg[gd];

    float bd0[KNN], bd1[KNN]; int bi0[KNN], bi1[KNN];
    #pragma unroll
    for (int k = 0; k < KNN; k++) { bd0[k]=3.0e38f; bd1[k]=3.0e38f; bi0[k]=0x3fffffff; bi1[k]=0x3fffffff; }

    for (int jj = 0; jj < JBL; jj++) {
        float4 c0 = sa[jj*4+0], c1 = sa[jj*4+1], c2 = sa[jj*4+2], c3 = sa[jj*4+3];
        #define DD(o,c) ((o).w + (c).w - 2.0f*((o).x*(c).x + (o).y*(c).y + (o).z*(c).z))
        float d = DD(o0,c0);
        d = fminf(d, DD(o0,c1)); d = fminf(d, DD(o0,c2)); d = fminf(d, DD(o0,c3));
        d = fminf(d, DD(o1,c0)); d = fminf(d, DD(o1,c1)); d = fminf(d, DD(o1,c2)); d = fminf(d, DD(o1,c3));
        d = fminf(d, DD(o2,c0)); d = fminf(d, DD(o2,c1)); d = fminf(d, DD(o2,c2)); d = fminf(d, DD(o2,c3));
        d = fminf(d, DD(o3,c0)); d = fminf(d, DD(o3,c1)); d = fminf(d, DD(o3,c2)); d = fminf(d, DD(o3,c3));
        #undef DD
        int j = jbase + jj;
        if (sseg[jj] == myseg) {
            if (j != ib) ins9(d, j, bd0, bi0);
        } else {
            ins9(d, j, bd1, bi1);
        }
    }
    size_t base = ((size_t)gd*JP + part)*2*KNN;
    #pragma unroll
    for (int k = 0; k < KNN; k++) {
        g_pD[base + k] = bd0[k];          g_pI[base + k] = bi0[k];
        g_pD[base + KNN + k] = bd1[k];    g_pI[base + KNN + k] = bi1[k];
    }
}

__global__ void k_knn_merge()
{
    int b = blockIdx.x*blockDim.x + threadIdx.x;
    if (b >= NB) return;
    int goff = (b >> 10) * NBG;
    #pragma unroll
    for (int list = 0; list < 2; list++) {
        float od[KNN]; int oi[KNN];
        #pragma unroll
        for (int k = 0; k < KNN; k++) { od[k]=3.1e38f; oi[k]=0x7fffffff; }
        for (int part = 0; part < JP; part++) {
            size_t base = ((size_t)b*JP + part)*2*KNN + list*KNN;
            #pragma unroll
            for (int k = 0; k < KNN; k++)
                ins9lex(g_pD[base+k], g_pI[base+k], od, oi);
        }
        #pragma unroll
        for (int k = 0; k < KNN; k++)
            g_nbr[b*NE + list*KNN + k] = goff + oi[k];
    }
}

// ---------------- 6. cp.async-pipelined fp16 tensor GEMM -------------------
// C[8192,512] = A @ W, A pre-packed fp16 A-frags, W fp16 B-frags.
// 128x128 CTA tile, 8 warps (2x4), BK=16, 4-stage cp.async smem pipeline.
// EPI 0: C = acc (fp32)
// EPI 1: C = addC + silu(acc) (fp32) + A-frag image of C (+ silu frags if WSILU)
// EPI 2: energy head — atomicAdd_row( silu(acc+bias)·W2 ), no C store.
template<int EPI, int WSILU>
__global__ __launch_bounds__(256,2) void gemm_p(
    const uint32_t* __restrict__ Af, const uint32_t* __restrict__ Bh,
    float* __restrict__ C, const float* __restrict__ addC,
    const float* __restrict__ bias, const float* __restrict__ W2p)
{
    __shared__ uint32_t sA[4][1024];    // [stage][mt(8)*lane(32)*4]
    __shared__ uint32_t sB[4][1024];    // [stage][ntg(16)*lane(32)*2]
    const int tid  = threadIdx.x;
    const int lane = tid & 31, wid = tid >> 5;
    const int wm = wid >> 2, wn = wid & 3;
    const int brow = blockIdx.y*128;
    const int bcol = blockIdx.x*128;
    const int gg = lane >> 2, tt = lane & 3;

    // copy sources: thread copies 16B of A (mt=wid) and 16B of B (ntg=tid>>4)
    const uint32_t* aSrc = Af + (((size_t)(blockIdx.y*8 + wid)*32)*32 + lane)*4;        // +128/panel
    const uint32_t* bSrc = Bh + ((size_t)(blockIdx.x*16 + (tid>>4))*32 + (tid&15)*2)*2; // +4096/panel
    uint32_t sAb = (uint32_t)__cvta_generic_to_shared(&sA[0][0]) + tid*16;
    uint32_t sBb = (uint32_t)__cvta_generic_to_shared(&sB[0][0]) + tid*16;

    float acc[4][4][4];
    #pragma unroll
    for (int mt=0;mt<4;mt++){
        #pragma unroll
        for (int nt=0;nt<4;nt++){
            #pragma unroll
            for (int r=0;r<4;r++) acc[mt][nt][r]=0.f;
        }
    }

    #pragma unroll
    for (int p0 = 0; p0 < 3; p0++) {
        cpa16(sAb + (p0&3)*4096, aSrc + p0*128);
        cpa16(sBb + (p0&3)*4096, bSrc + (size_t)p0*4096);
        asm volatile("cp.async.commit_group;" ::: "memory");
    }

    for (int p = 0; p < 32; p++) {
        if (p <= 29)      asm volatile("cp.async.wait_group 2;" ::: "memory");
        else if (p == 30) asm volatile("cp.async.wait_group 1;" ::: "memory");
        else              asm volatile("cp.async.wait_group 0;" ::: "memory");
        __syncthreads();
        int s = p & 3;
        uint32_t af[4][4], bf[4][2];
        #pragma unroll
        for (int mt=0;mt<4;mt++)
            *(uint4*)af[mt] = *(const uint4*)&sA[s][((wm*4+mt)*32+lane)*4];
        #pragma unroll
        for (int nt=0;nt<4;nt++)
            *(uint2*)bf[nt] = *(const uint2*)&sB[s][((wn*4+nt)*32+lane)*2];
        #pragma unroll
        for (int mt=0;mt<4;mt++){
            #pragma unroll
            for (int nt=0;nt<4;nt++)
                mma16(acc[mt][nt], af[mt], bf[nt]);
        }
        if (p + 3 < 32) {
            int q = p + 3;
            cpa16(sAb + (q&3)*4096, aSrc + q*128);
            cpa16(sBb + (q&3)*4096, bSrc + (size_t)q*4096);
            asm volatile("cp.async.commit_group;" ::: "memory");
        }
    }

    // epilogue
    #pragma unroll
    for (int mt=0;mt<4;mt++){
        int row0 = brow + wm*64 + mt*16 + gg;
        int row1 = row0 + 8;
        float es0 = 0.f, es1 = 0.f;
        #pragma unroll
        for (int nt=0;nt<4;nt++){
            int col = bcol + wn*32 + nt*8 + 2*tt;
            float v0 = acc[mt][nt][0], v1 = acc[mt][nt][1];
            float v2 = acc[mt][nt][2], v3 = acc[mt][nt][3];
            if (EPI == 1) {
                float2 c0 = *(const float2*)(addC + (size_t)row0*HID + col);
                float2 c1 = *(const float2*)(addC + (size_t)row1*HID + col);
                v0 = c0.x + silu_f(v0); v1 = c0.y + silu_f(v1);
                v2 = c1.x + silu_f(v2); v3 = c1.y + silu_f(v3);
                store_frag(g_hf, row0, col, v0, v1);
                store_frag(g_hf, row1, col, v2, v3);
                if (WSILU) {
                    store_frag(g_shf, row0, col, silu_f(v0), silu_f(v1));
                    store_frag(g_shf, row1, col, silu_f(v2), silu_f(v3));
                }
            }
            if (EPI == 2) {
                float2 bb = *(const float2*)(bias + col);
                float2 w2 = *(const float2*)(W2p + col);
                v0 += bb.x; v1 += bb.y; v2 += bb.x; v3 += bb.y;
                es0 += silu_f(v0)*w2.x + silu_f(v1)*w2.y;
                es1 += silu_f(v2)*w2.x + silu_f(v3)*w2.y;
            } else {
                float2 o0; o0.x=v0; o0.y=v1;
                float2 o1; o1.x=v2; o1.y=v3;
                *(float2*)(C + (size_t)row0*HID + col) = o0;
                *(float2*)(C + (size_t)row1*HID + col) = o1;
            }
        }
        if (EPI == 2) {
            atomicAdd(&g_eblk[row0], es0);
            atomicAdd(&g_eblk[row1], es1);
        }
    }
}

// ---------------- 7. fused edge/message kernel (agg -> frags) --------------
__global__ __launch_bounds__(128) void k_edge(
    const float* __restrict__ wz_l, const float* __restrict__ eWl,
    const float* __restrict__ Zb_old, float* __restrict__ Zb_new)
{
    int d = blockIdx.x;
    int tid = threadIdx.x;
    const float4* hW4 = (const float4*)g_hW;
    float4 hd  = hW4[(size_t)d*128 + tid];
    float4 wzv = ((const float4*)wz_l)[tid];
    float4 ew0 = ((const float4*)eWl)[tid];
    float4 ew1 = ((const float4*)(eWl + HID))[tid];
    float4 ag = make_float4(0.f,0.f,0.f,0.f);

    __shared__ int   snbr[NE];
    __shared__ float sp[NE][4];
    __shared__ float sx[NE], sy[NE], sz[NE];
    if (tid < NE) snbr[tid] = g_nbr[d*NE + tid];
    __syncthreads();

    int wid = tid >> 5, lane = tid & 31;
    #pragma unroll
    for (int e = 0; e < NE; e++) {
        int s = snbr[e];
        float4 ew = (e < KNN) ? ew0 : ew1;
        float4 hs = hW4[(size_t)s*128 + tid];
        float m0 = silu_f(hs.x + hd.x + ew.x);
        float m1 = silu_f(hs.y + hd.y + ew.y);
        float m2 = silu_f(hs.z + hd.z + ew.z);
        float m3 = silu_f(hs.w + hd.w + ew.w);
        ag.x += m0; ag.y += m1; ag.z += m2; ag.w += m3;
        float p = m0*wzv.x + m1*wzv.y + m2*wzv.z + m3*wzv.w;
        #pragma unroll
        for (int off = 16; off; off >>= 1) p += __shfl_down_sync(0xffffffffu, p, off);
        if (lane == 0) sp[e][wid] = p;
    }
    __syncthreads();

    float Zdx = Zb_old[d*3+0], Zdy = Zb_old[d*3+1], Zdz = Zb_old[d*3+2];
    if (tid < NE) {
        float coef = tanhf(sp[tid][0] + sp[tid][1] + sp[tid][2] + sp[tid][3]);
        int s = snbr[tid];
        sx[tid] = (Zb_old[s*3+0] - Zdx)*coef;
        sy[tid] = (Zb_old[s*3+1] - Zdy)*coef;
        sz[tid] = (Zb_old[s*3+2] - Zdz)*coef;
    }
    __syncthreads();

    store_frag(g_aggf, d, 4*tid,   ag.x, ag.y);
    store_frag(g_aggf, d, 4*tid+2, ag.z, ag.w);
    if (tid == 0) {
        float zx=0.f, zy=0.f, zz=0.f;
        #pragma unroll
        for (int e = 0; e < NE; e++) { zx += sx[e]; zy += sy[e]; zz += sz[e]; }
        const float inv = 1.0f / (2*KNN);
        Zb_new[d*3+0] = Zdx + zx*inv;
        Zb_new[d*3+1] = Zdy + zy*inv;
        Zb_new[d*3+2] = Zdz + zz*inv;
    }
}

// ---------------- 8. energy reduce ----------------
__global__ __launch_bounds__(256) void k_energy(float* __restrict__ out)
{
    int g = blockIdx.x;
    int tid = threadIdx.x;
    float p = 0.f;
    #pragma unroll
    for (int k = 0; k < 4; k++) p += g_eblk[g*NBG + k*256 + tid];
    __shared__ float sred[8];
    #pragma unroll
    for (int off = 16; off; off >>= 1) p += __shfl_down_sync(0xffffffffu, p, off);
    if ((tid & 31) == 0) sred[tid >> 5] = p;
    __syncthreads();
    if (tid == 0) {
        float s = 0.f;
        #pragma unroll
        for (int w = 0; w < 8; w++) s += sred[w];
        out[OFF_E + g] = s;
        if (g == 0) out[OFF_LOSS] = 0.f;
    }
}

// ---------------- 9. graph_repr (two-phase) ----------------
__global__ __launch_bounds__(512) void k_graphp()
{
    int g = blockIdx.y;
    int chunk = blockIdx.x;
    int tid = threadIdx.x;
    float acc = 0.f;
    const float* hp = g_h + (size_t)(g*NBG + chunk*128)*HID + tid;
    for (int b = 0; b < 128; b++) acc += hp[(size_t)b*HID];
    g_gpart[(g*8 + chunk)*HID + tid] = acc;
}

__global__ __launch_bounds__(512) void k_graph2(float* __restrict__ out)
{
    int g = blockIdx.x;
    int tid = threadIdx.x;
    float acc = 0.f;
    #pragma unroll
    for (int c = 0; c < 8; c++) acc += g_gpart[(g*8 + c)*HID + tid];
    out[OFF_GR + g*HID + tid] = acc;
}

// ---------------- 10. pred_noise + loss ----------------
__global__ __launch_bounds__(256) void k_noise_loss(const float* __restrict__ noise,
                                                    float* __restrict__ out)
{
    int u = blockIdx.x*blockDim.x + threadIdx.x;
    float local = 0.f;
    if (u < NU) {
        int b = u >> 2;
        float dx = g_ZbB[b*3+0] - g_Zb0[b*3+0];
        float dy = g_ZbB[b*3+1] - g_Zb0[b*3+1];
        float dz = g_ZbB[b*3+2] - g_Zb0[b*3+2];
        out[OFF_PN + u*3+0] = dx;
        out[OFF_PN + u*3+1] = dy;
        out[OFF_PN + u*3+2] = dz;
        float ex = dx - noise[u*3+0];
        float ey = dy - noise[u*3+1];
        float ez = dz - noise[u*3+2];
        local = ex*ex + ey*ey + ez*ez;
    }
    __shared__ float sred[8];
    float p = local;
    #pragma unroll
    for (int off = 16; off; off >>= 1) p += __shfl_down_sync(0xffffffffu, p, off);
    if ((threadIdx.x & 31) == 0) sred[threadIdx.x >> 5] = p;
    __syncthreads();
    if (threadIdx.x == 0) {
        float s = 0.f;
        #pragma unroll
        for (int w = 0; w < 8; w++) s += sred[w];
        atomicAdd(out + OFF_LOSS, s * 0.0625f);
    }
}

// ---------------- 11. unit_repr & block_repr ----------------
__global__ void k_unit(float* __restrict__ out)
{
    int idx = blockIdx.x*blockDim.x + threadIdx.x;
    if (idx >= NU*(HID/4)) return;
    int u = idx >> 7;
    int c = idx & 127;
    float4 h0 = ((const float4*)g_H0)[idx];
    float4 hb = ((const float4*)g_h)[(size_t)(u>>2)*128 + c];
    float4 r; r.x=h0.x+hb.x; r.y=h0.y+hb.y; r.z=h0.z+hb.z; r.w=h0.w+hb.w;
    ((float4*)(out + OFF_UR))[idx] = r;
}

__global__ void k_brepr(float* __restrict__ out)
{
    int idx = blockIdx.x*blockDim.x + threadIdx.x;
    if (idx >= NB*(HID/4)) return;
    ((float4*)(out + OFF_BR))[idx] = ((const float4*)g_h)[idx];
}

// ---------------- launch ----------------
extern "C" void kernel_launch(void* const* d_in, const int* in_sizes, int n_in,
                              void* d_out, int out_size)
{
    const float* Z         = (const float*)d_in[0];
    const int*   B         = (const int*)  d_in[1];
    const int*   A         = (const int*)  d_in[2];
    const int*   AP        = (const int*)  d_in[3];
    const int*   seg       = (const int*)  d_in[6];
    const float* noise     = (const float*)d_in[7];
    const int*   nl        = (const int*)  d_in[8];
    const float* sigmas    = (const float*)d_in[9];
    const float* atom_emb  = (const float*)d_in[10];
    const float* pos_emb   = (const float*)d_in[11];
    const float* block_emb = (const float*)d_in[12];
    const float* edge_emb  = (const float*)d_in[13];
    const float* Wm        = (const float*)d_in[14];
    const float* We        = (const float*)d_in[15];
    const float* Wu        = (const float*)d_in[16];
    const float* wz        = (const float*)d_in[17];
    const float* W1        = (const float*)d_in[18];
    const float* b1        = (const float*)d_in[19];
    const float* W2        = (const float*)d_in[20];
    float* out = (float*)d_out;

    float *p_h, *p_hW, *p_ZbA, *p_ZbB, *p_eW;
    uint32_t *p_Wh, *p_hf, *p_aggf, *p_shf;
    cudaGetSymbolAddress((void**)&p_h,    g_h);
    cudaGetSymbolAddress((void**)&p_hW,   g_hW);
    cudaGetSymbolAddress((void**)&p_ZbA,  g_ZbA);
    cudaGetSymbolAddress((void**)&p_ZbB,  g_ZbB);
    cudaGetSymbolAddress((void**)&p_eW,   g_eW);
    cudaGetSymbolAddress((void**)&p_Wh,   g_Wh);
    cudaGetSymbolAddress((void**)&p_hf,   g_hf);
    cudaGetSymbolAddress((void**)&p_aggf, g_aggf);
    cudaGetSymbolAddress((void**)&p_shf,  g_shf);

    k_perturb<<<(NB+255)/256, 256>>>(Z, noise, nl, sigmas);
    k_H0h<<<NB, 128>>>(A, AP, B, atom_emb, pos_emb, block_emb);
    k_ew<<<(LAY*2*HID+255)/256, 256>>>(edge_emb, We);
    k_wprep_h<<<dim3(32, 7), 256>>>(Wm, Wu, W1);

    k_knn_part<<<dim3(JP, 4, G), 256>>>(seg);
    k_knn_merge<<<(NB+255)/256, 256>>>();

    const size_t WSTRIDE = (size_t)32*64*32*2;
    float* zold = p_ZbA;
    float* znew = p_ZbB;
    for (int l = 0; l < LAY; l++) {
        gemm_p<0,0><<<dim3(4,64), 256>>>(p_hf, p_Wh + (size_t)l*WSTRIDE,
                                         p_hW, nullptr, nullptr, nullptr);
        k_edge<<<NB, 128>>>(wz + l*HID, p_eW + l*2*HID, zold, znew);
        if (l < LAY-1)
            gemm_p<1,0><<<dim3(4,64), 256>>>(p_aggf, p_Wh + (size_t)(3+l)*WSTRIDE,
                                             p_h, p_h, nullptr, nullptr);
        else
            gemm_p<1,1><<<dim3(4,64), 256>>>(p_aggf, p_Wh + (size_t)(3+l)*WSTRIDE,
                                             p_h, p_h, nullptr, nullptr);
        float* tmp = zold; zold = znew; znew = tmp;
    }
    // after 3 swaps the final Zb lives in g_ZbB

    gemm_p<2,0><<<dim3(4,64), 256>>>(p_shf, p_Wh + (size_t)6*WSTRIDE,
                                     nullptr, nullptr, b1, W2);
    k_energy<<<G, 256>>>(out);
    k_graphp<<<dim3(8, G), 512>>>();
    k_graph2<<<G, 512>>>(out);
    k_noise_loss<<<(NU+255)/256, 256>>>(noise, out);
    k_unit<<<(NU*(HID/4)+255)/256, 256>>>(out);
    k_brepr<<<(NB*(HID/4)+255)/256, 256>>>(out);
}